// round 10
// baseline (speedup 1.0000x reference)
#include <cuda_runtime.h>
#include <cuda_bf16.h>
#include <cstdint>

#define HGRID 768
#define WGRID 768
#define NMAX  200064   // 1563 * 128

// Scratch in __device__ globals (no allocation allowed).
__device__ int g_idx_map[HGRID * WGRID];
// h1 as interleaved bf16 split planes: per row {128B hi, 128B lo}
__device__ __align__(16) unsigned char g_h1b[(size_t)NMAX * 256];
// B fragments (uint4 = {bhi0,bhi1,blo0,blo1}):
__device__ uint4 g_w2f[9 * 4 * 8 * 32];   // w2: [tap][kc(4)][nt(8)][lane(32)]
__device__ uint4 g_w3f[4 * 4 * 8 * 32];   // w3: [cb(4)][kc(4)][nt(8)][lane(32)]

// ---------------------------------------------------------------------------
__device__ __forceinline__ int coords_is64(const int* c) { return c[1] == 0; }
__device__ __forceinline__ int load_coord(const int* c, int is64, int i) {
    return is64 ? c[2 * i] : c[i];
}
__device__ __forceinline__ void bsplit2(float a, float b, uint32_t& hi, uint32_t& lo) {
    __nv_bfloat16 ah = __float2bfloat16(a);
    __nv_bfloat16 bh = __float2bfloat16(b);
    float ar = a - __bfloat162float(ah);
    float br = b - __bfloat162float(bh);
    __nv_bfloat162 h; h.x = ah; h.y = bh;
    __nv_bfloat162 l; l.x = __float2bfloat16(ar); l.y = __float2bfloat16(br);
    hi = *reinterpret_cast<uint32_t*>(&h);
    lo = *reinterpret_cast<uint32_t*>(&l);
}

// mma.sync m16n8k16 bf16 -> f32 accumulate
__device__ __forceinline__ void mma16816(float c[4], const uint32_t a[4],
                                         uint32_t b0, uint32_t b1) {
    asm volatile(
        "mma.sync.aligned.m16n8k16.row.col.f32.bf16.bf16.f32 "
        "{%0,%1,%2,%3}, {%4,%5,%6,%7}, {%8,%9}, {%0,%1,%2,%3};"
        : "+f"(c[0]), "+f"(c[1]), "+f"(c[2]), "+f"(c[3])
        : "r"(a[0]), "r"(a[1]), "r"(a[2]), "r"(a[3]), "r"(b0), "r"(b1));
}

// ---------------------------------------------------------------------------
// util1: clear idx_map (all threads) + prep w2 B-fragments (first 9216)
__global__ void util1_kernel(const float* __restrict__ w2) {
    int i = blockIdx.x * blockDim.x + threadIdx.x;
    if (i < HGRID * WGRID) g_idx_map[i] = -1;
    if (i < 9 * 4 * 8 * 32) {
        int lane = i & 31, nt = (i >> 5) & 7, kc = (i >> 8) & 3, tap = i >> 10;
        int n  = nt * 8 + (lane >> 2);
        int k0 = kc * 16 + (lane & 3) * 2;
        uint32_t hi[2], lo[2];
#pragma unroll
        for (int j = 0; j < 2; ++j) {
            int k = k0 + j * 8;
            bsplit2(w2[tap * 4096 + k * 64 + n], w2[tap * 4096 + (k + 1) * 64 + n],
                    hi[j], lo[j]);
        }
        g_w2f[i] = make_uint4(hi[0], hi[1], lo[0], lo[1]);
    }
}

// util2: scatter coords -> idx_map + prep w3 B-fragments (first 4096)
__global__ void util2_kernel(const int* __restrict__ coords,
                             const float* __restrict__ w3, int n) {
    int i = blockIdx.x * blockDim.x + threadIdx.x;
    if (i < n) {
        int is64 = coords_is64(coords);
        g_idx_map[load_coord(coords, is64, i)] = i;
    }
    if (i < 4 * 4 * 8 * 32) {
        int lane = i & 31, nt = (i >> 5) & 7, kc = (i >> 8) & 3, cb = i >> 10;
        int nn = cb * 64 + nt * 8 + (lane >> 2);
        int k0 = kc * 16 + (lane & 3) * 2;
        uint32_t hi[2], lo[2];
#pragma unroll
        for (int j = 0; j < 2; ++j) {
            int k = k0 + j * 8;
            bsplit2(w3[k * 256 + nn], w3[(k + 1) * 256 + nn], hi[j], lo[j]);
        }
        g_w3f[i] = make_uint4(hi[0], hi[1], lo[0], lo[1]);
    }
}

// ---------------------------------------------------------------------------
// FFMA micro-kernel (conv1)
template <int LDA>
__device__ __forceinline__ void mm32(const float* __restrict__ sA,
                                     const float* __restrict__ sB,
                                     int trow, int tcol, float acc[8][4]) {
#pragma unroll
    for (int k = 0; k < 32; ++k) {
        float4 b = *(const float4*)(sB + k * 64 + tcol);
#pragma unroll
        for (int i = 0; i < 8; ++i) {
            float a = sA[(trow + i) * LDA + k];
            acc[i][0] = fmaf(a, b.x, acc[i][0]);
            acc[i][1] = fmaf(a, b.y, acc[i][1]);
            acc[i][2] = fmaf(a, b.z, acc[i][2]);
            acc[i][3] = fmaf(a, b.w, acc[i][3]);
        }
    }
}

// conv1: h1 = relu((feats @ w1) * s1 + b1) -> bf16 hi/lo planes  (R5 version)
__global__ void __launch_bounds__(256) conv1_kernel(
    const float* __restrict__ feats, const float* __restrict__ w1,
    const float* __restrict__ s1, const float* __restrict__ b1, int n)
{
    __shared__ __align__(16) float sA[128 * 33];
    __shared__ __align__(16) float sB[32 * 64];
    const int tid = threadIdx.x;
    const int site0 = blockIdx.x * 128;
    const int trow = (tid >> 4) << 3;
    const int tcol = (tid & 15) << 2;

    float acc[8][4];
#pragma unroll
    for (int i = 0; i < 8; ++i)
#pragma unroll
        for (int j = 0; j < 4; ++j) acc[i][j] = 0.f;

#pragma unroll 1
    for (int k0 = 0; k0 < 256; k0 += 32) {
#pragma unroll
        for (int l = 0; l < 4; ++l) {
            int i = tid + l * 256;
            int r = i >> 3, c4 = (i & 7) << 2;
            int site = site0 + r;
            float4 v = make_float4(0.f, 0.f, 0.f, 0.f);
            if (site < n) v = *(const float4*)&feats[(size_t)site * 256 + k0 + c4];
            sA[r * 33 + c4 + 0] = v.x; sA[r * 33 + c4 + 1] = v.y;
            sA[r * 33 + c4 + 2] = v.z; sA[r * 33 + c4 + 3] = v.w;
        }
#pragma unroll
        for (int l = 0; l < 2; ++l) {
            int i = tid + l * 256;
            int r = i >> 4, c4 = (i & 15) << 2;
            *(float4*)&sB[r * 64 + c4] = *(const float4*)&w1[(size_t)(k0 + r) * 64 + c4];
        }
        __syncthreads();
        mm32<33>(sA, sB, trow, tcol, acc);
        __syncthreads();
    }

    float sc[4], bi[4];
#pragma unroll
    for (int j = 0; j < 4; ++j) { sc[j] = s1[tcol + j]; bi[j] = b1[tcol + j]; }
#pragma unroll
    for (int i = 0; i < 8; ++i) {
        int site = site0 + trow + i;   // < NMAX always; OOB rows never read back
        float v0 = fmaxf(fmaf(acc[i][0], sc[0], bi[0]), 0.f);
        float v1 = fmaxf(fmaf(acc[i][1], sc[1], bi[1]), 0.f);
        float v2 = fmaxf(fmaf(acc[i][2], sc[2], bi[2]), 0.f);
        float v3 = fmaxf(fmaf(acc[i][3], sc[3], bi[3]), 0.f);
        uint32_t h0, l0, h1v, l1v;
        bsplit2(v0, v1, h0, l0);
        bsplit2(v2, v3, h1v, l1v);
        unsigned char* row = g_h1b + (size_t)site * 256;
        *(uint2*)(row + tcol * 2)       = make_uint2(h0, h1v);   // hi plane
        *(uint2*)(row + 128 + tcol * 2) = make_uint2(l0, l1v);   // lo plane
    }
}

// ---------------------------------------------------------------------------
// FUSED conv2 + conv3 (block-phased; COALESCED gather: 16 lanes per 256B row):
//   h2 = relu(sparse3x3(h1) * s2 + b2)   (registers only, never stored)
//   out = relu((h2 @ w3) * s3 + b3 + feats)
#define LDP 144                        // bytes per row per plane
#define PLANE (128 * LDP)              // 18432
// dynamic smem layout (bytes):
#define SM_SC    0                     // 640 floats = 2560
#define SM_NBR   2560                  // 9*128*4 = 4608
#define SM_A     7680                  // 2 * PLANE = 36864 (hi, lo planes)
#define SM_B     (SM_A + 2 * PLANE)    // 44544: 1024 uint4 = 16384
#define SM_TOTAL (SM_B + 16384)        // 60928

__global__ void __launch_bounds__(256) conv23_kernel(
    const int* __restrict__ coords,
    const float* __restrict__ s2, const float* __restrict__ b2,
    const float* __restrict__ feats,
    const float* __restrict__ s3, const float* __restrict__ b3,
    float* __restrict__ out, int n)
{
    extern __shared__ __align__(128) char dsm[];
    float* s_s2 = (float*)(dsm + SM_SC);
    float* s_b2 = s_s2 + 64;
    float* s_s3 = s_b2 + 64;
    float* s_b3 = s_s3 + 256;
    int*  s_nbr = (int*)(dsm + SM_NBR);
    unsigned char* Abuf = (unsigned char*)(dsm + SM_A);
    uint4* Bsm = (uint4*)(dsm + SM_B);

    const int tid = threadIdx.x, wid = tid >> 5, lane = tid & 31;
    const int site0 = blockIdx.x * 128;
    const int rw = wid * 16;

    // coalesced 256B-row access mapping: 16 lanes cover one row
    const int sub  = lane >> 4;          // which row of the pair
    const int boff = (lane & 15) * 16;   // byte chunk within 256B row
    const int psel = boff >> 7;          // 0 = hi plane, 1 = lo plane
    const int poff = boff & 127;         // byte within plane row

    if (tid < 64) { s_s2[tid] = s2[tid]; s_b2[tid] = b2[tid]; }
    s_s3[tid] = s3[tid]; s_b3[tid] = b3[tid];
    if (tid < 128) {
#pragma unroll
        for (int t = 0; t < 9; ++t) s_nbr[t * 128 + tid] = -1;
        int site = site0 + tid;
        if (site < n) {
            int is64 = coords_is64(coords);
            int c = load_coord(coords, is64, site);
            int y = c / WGRID, x = c % WGRID;
#pragma unroll
            for (int t = 0; t < 9; ++t) {
                int ny = y + t / 3 - 1, nx = x + t % 3 - 1;
                if (ny >= 0 && ny < HGRID && nx >= 0 && nx < WGRID)
                    s_nbr[t * 128 + tid] = g_idx_map[ny * WGRID + nx];
            }
        }
    }
    __syncthreads();

    float acc[8][4];
#pragma unroll
    for (int t = 0; t < 8; ++t)
#pragma unroll
        for (int j = 0; j < 4; ++j) acc[t][j] = 0.f;

    // ---------------- conv2: 9-tap sparse 3x3 accumulation ----------------
#pragma unroll 1
    for (int tap = 0; tap < 9; ++tap) {
        {   // coalesced gather: warp covers its 16 rows in 8 iters x 2 rows
            // per LDG instr: 2 source rows x 2 lines = 4 wavefronts
#pragma unroll
            for (int g = 0; g < 8; ++g) {
                int row = rw + g * 2 + sub;
                int nb = s_nbr[tap * 128 + row];
                uint4 v = make_uint4(0, 0, 0, 0);
                if (nb >= 0)
                    v = *(const uint4*)(g_h1b + (size_t)nb * 256 + boff);
                *(uint4*)(Abuf + psel * PLANE + row * LDP + poff) = v;
            }
        }
        {   // stage this tap's B fragments into smem (16KB, 64B/thread)
            const uint4* bs = g_w2f + (size_t)tap * 1024 + tid * 4;
#pragma unroll
            for (int q = 0; q < 4; ++q) Bsm[tid * 4 + q] = bs[q];
        }
        __syncthreads();

        // MMA: A from smem planes, B from smem fragments (LDS only)
#pragma unroll
        for (int kc = 0; kc < 4; ++kc) {
            uint32_t ab = (uint32_t)((rw + (lane >> 2)) * LDP + kc * 32 + (lane & 3) * 4);
            uint32_t ah[4], al[4];
            ah[0] = *(const uint32_t*)(Abuf + ab);
            ah[1] = *(const uint32_t*)(Abuf + ab + 8 * LDP);
            ah[2] = *(const uint32_t*)(Abuf + ab + 16);
            ah[3] = *(const uint32_t*)(Abuf + ab + 8 * LDP + 16);
            al[0] = *(const uint32_t*)(Abuf + PLANE + ab);
            al[1] = *(const uint32_t*)(Abuf + PLANE + ab + 8 * LDP);
            al[2] = *(const uint32_t*)(Abuf + PLANE + ab + 16);
            al[3] = *(const uint32_t*)(Abuf + PLANE + ab + 8 * LDP + 16);
#pragma unroll
            for (int nt = 0; nt < 8; ++nt) {
                uint4 b = Bsm[kc * 256 + nt * 32 + lane];
                mma16816(acc[nt], ah, b.x, b.y);
                mma16816(acc[nt], ah, b.z, b.w);
                mma16816(acc[nt], al, b.x, b.y);
            }
        }
        __syncthreads();   // A/B consumers done before next tap's writes
    }

    // ------- bn2 + relu in registers; repackage C-frags as A-frags --------
    uint32_t fh[4][4], fl[4][4];
    {
        const int n0 = (lane & 3) * 2;
#pragma unroll
        for (int kc = 0; kc < 4; ++kc) {
#pragma unroll
            for (int q = 0; q < 2; ++q) {
                int nt = 2 * kc + q;
                int c0 = nt * 8 + n0;
                float v0 = fmaxf(fmaf(acc[nt][0], s_s2[c0],     s_b2[c0]),     0.f);
                float v1 = fmaxf(fmaf(acc[nt][1], s_s2[c0 + 1], s_b2[c0 + 1]), 0.f);
                float v2 = fmaxf(fmaf(acc[nt][2], s_s2[c0],     s_b2[c0]),     0.f);
                float v3 = fmaxf(fmaf(acc[nt][3], s_s2[c0 + 1], s_b2[c0 + 1]), 0.f);
                bsplit2(v0, v1, fh[kc][2 * q],     fl[kc][2 * q]);
                bsplit2(v2, v3, fh[kc][2 * q + 1], fl[kc][2 * q + 1]);
            }
        }
    }

    // ---------------- conv3: 4 column blocks of 64, from registers --------
    float* stg = (float*)Abuf;   // 128 x 64 f32 staging = 32KB (fits A buffer)
    {   // preload cb=0 B fragments
        const uint4* bs = g_w3f + tid * 4;
#pragma unroll
        for (int q = 0; q < 4; ++q) Bsm[tid * 4 + q] = bs[q];
    }
    __syncthreads();

#pragma unroll 1
    for (int cb = 0; cb < 4; ++cb) {
        float acc2[8][4];
#pragma unroll
        for (int t = 0; t < 8; ++t)
#pragma unroll
            for (int j = 0; j < 4; ++j) acc2[t][j] = 0.f;

#pragma unroll
        for (int kc = 0; kc < 4; ++kc) {
#pragma unroll
            for (int nt = 0; nt < 8; ++nt) {
                uint4 b = Bsm[kc * 256 + nt * 32 + lane];
                mma16816(acc2[nt], fh[kc], b.x, b.y);
                mma16816(acc2[nt], fh[kc], b.z, b.w);
                mma16816(acc2[nt], fl[kc], b.x, b.y);
            }
        }
        __syncthreads();   // B reads done; stg free (prev write-out done)
        {
            int r0 = rw + (lane >> 2);
            int n0 = (lane & 3) * 2;
#pragma unroll
            for (int nt = 0; nt < 8; ++nt) {
                int c  = nt * 8 + n0;
                int cg = cb * 64 + c;
                stg[r0 * 64 + c]           = fmaf(acc2[nt][0], s_s3[cg],     s_b3[cg]);
                stg[r0 * 64 + c + 1]       = fmaf(acc2[nt][1], s_s3[cg + 1], s_b3[cg + 1]);
                stg[(r0 + 8) * 64 + c]     = fmaf(acc2[nt][2], s_s3[cg],     s_b3[cg]);
                stg[(r0 + 8) * 64 + c + 1] = fmaf(acc2[nt][3], s_s3[cg + 1], s_b3[cg + 1]);
            }
        }
        if (cb < 3) {   // stage next cb's B fragments
            const uint4* bs = g_w3f + (size_t)(cb + 1) * 1024 + tid * 4;
#pragma unroll
            for (int q = 0; q < 4; ++q) Bsm[tid * 4 + q] = bs[q];
        }
        __syncthreads();   // stg + next B visible
        {   // coalesced residual+relu+write: 2 sites per instr, 4 lines
#pragma unroll
            for (int g = 0; g < 8; ++g) {
                int row = rw + g * 2 + sub;
                int site = site0 + row;
                if (site < n) {
                    float4 a = *(const float4*)((const char*)stg + row * 256 + boff);
                    float4 b = *(const float4*)((const char*)feats +
                                                (size_t)site * 1024 + cb * 256 + boff);
                    float4 o;
                    o.x = fmaxf(a.x + b.x, 0.f);
                    o.y = fmaxf(a.y + b.y, 0.f);
                    o.z = fmaxf(a.z + b.z, 0.f);
                    o.w = fmaxf(a.w + b.w, 0.f);
                    *(float4*)((char*)out + (size_t)site * 1024 + cb * 256 + boff) = o;
                }
            }
        }
    }
}

// ---------------------------------------------------------------------------
extern "C" void kernel_launch(void* const* d_in, const int* in_sizes, int n_in,
                              void* d_out, int out_size) {
    const float* feats  = (const float*)d_in[0];
    const int*   coords = (const int*)d_in[1];
    const float* w1     = (const float*)d_in[2];
    const float* w2     = (const float*)d_in[3];
    const float* w3     = (const float*)d_in[4];
    const float* s1     = (const float*)d_in[5];
    const float* b1     = (const float*)d_in[6];
    const float* s2     = (const float*)d_in[7];
    const float* b2     = (const float*)d_in[8];
    const float* s3     = (const float*)d_in[9];
    const float* b3     = (const float*)d_in[10];
    float* out = (float*)d_out;

    const int n = in_sizes[0] / 256;
    const int tiles = (n + 127) / 128;

    cudaFuncSetAttribute(conv23_kernel,
                         cudaFuncAttributeMaxDynamicSharedMemorySize, SM_TOTAL);

    // 4 launches; conv23 is launch #4 so ncu (-s/-c window) captures it.
    util1_kernel<<<(HGRID * WGRID + 255) / 256, 256>>>(w2);                 // #1
    util2_kernel<<<(max(n, 4096) + 255) / 256, 256>>>(coords, w3, n);       // #2
    conv1_kernel<<<tiles, 256>>>(feats, w1, s1, b1, n);                     // #3
    conv23_kernel<<<tiles, 256, SM_TOTAL>>>(coords, s2, b2, feats, s3, b3, out, n);  // #4
}

// round 12
// speedup vs baseline: 1.7154x; 1.7154x over previous
#include <cuda_runtime.h>
#include <cuda_bf16.h>
#include <cstdint>

#define HGRID 768
#define WGRID 768
#define NMAX  200064   // 1563 * 128

// Scratch in __device__ globals (no allocation allowed).
__device__ int g_idx_map[HGRID * WGRID];
// h1 as interleaved bf16 split planes: per row {128B hi, 128B lo}
__device__ __align__(16) unsigned char g_h1b[(size_t)NMAX * 256];
// B fragments (uint4 = {bhi0,bhi1,blo0,blo1}):
__device__ uint4 g_w2f[9 * 4 * 8 * 32];   // w2: [tap][kc(4)][nt(8)][lane(32)]
__device__ uint4 g_w3f[4 * 4 * 8 * 32];   // w3: [cb(4)][kc(4)][nt(8)][lane(32)]

// ---------------------------------------------------------------------------
__device__ __forceinline__ int coords_is64(const int* c) { return c[1] == 0; }
__device__ __forceinline__ int load_coord(const int* c, int is64, int i) {
    return is64 ? c[2 * i] : c[i];
}
__device__ __forceinline__ void bsplit2(float a, float b, uint32_t& hi, uint32_t& lo) {
    __nv_bfloat16 ah = __float2bfloat16(a);
    __nv_bfloat16 bh = __float2bfloat16(b);
    float ar = a - __bfloat162float(ah);
    float br = b - __bfloat162float(bh);
    __nv_bfloat162 h; h.x = ah; h.y = bh;
    __nv_bfloat162 l; l.x = __float2bfloat16(ar); l.y = __float2bfloat16(br);
    hi = *reinterpret_cast<uint32_t*>(&h);
    lo = *reinterpret_cast<uint32_t*>(&l);
}
__device__ __forceinline__ uint32_t smem_u32(const void* p) {
    uint32_t a;
    asm("{ .reg .u64 t; cvta.to.shared.u64 t, %1; cvt.u32.u64 %0, t; }"
        : "=r"(a) : "l"(p));
    return a;
}
// L2-direct async copy (bypasses L1 -> no pollution of anything)
__device__ __forceinline__ void cp_async16_cg(uint32_t dst, const void* src, int srcsize) {
    asm volatile("cp.async.cg.shared.global [%0], [%1], 16, %2;"
                 :: "r"(dst), "l"(src), "r"(srcsize) : "memory");
}
#define CP_COMMIT() asm volatile("cp.async.commit_group;" ::: "memory")
#define CP_WAIT0()  asm volatile("cp.async.wait_group 0;" ::: "memory")

// mma.sync m16n8k16 bf16 -> f32 accumulate
__device__ __forceinline__ void mma16816(float c[4], const uint32_t a[4],
                                         uint32_t b0, uint32_t b1) {
    asm volatile(
        "mma.sync.aligned.m16n8k16.row.col.f32.bf16.bf16.f32 "
        "{%0,%1,%2,%3}, {%4,%5,%6,%7}, {%8,%9}, {%0,%1,%2,%3};"
        : "+f"(c[0]), "+f"(c[1]), "+f"(c[2]), "+f"(c[3])
        : "r"(a[0]), "r"(a[1]), "r"(a[2]), "r"(a[3]), "r"(b0), "r"(b1));
}

// ---------------------------------------------------------------------------
// util1: clear idx_map (all threads) + prep w2 B-fragments (first 9216)
__global__ void util1_kernel(const float* __restrict__ w2) {
    int i = blockIdx.x * blockDim.x + threadIdx.x;
    if (i < HGRID * WGRID) g_idx_map[i] = -1;
    if (i < 9 * 4 * 8 * 32) {
        int lane = i & 31, nt = (i >> 5) & 7, kc = (i >> 8) & 3, tap = i >> 10;
        int n  = nt * 8 + (lane >> 2);
        int k0 = kc * 16 + (lane & 3) * 2;
        uint32_t hi[2], lo[2];
#pragma unroll
        for (int j = 0; j < 2; ++j) {
            int k = k0 + j * 8;
            bsplit2(w2[tap * 4096 + k * 64 + n], w2[tap * 4096 + (k + 1) * 64 + n],
                    hi[j], lo[j]);
        }
        g_w2f[i] = make_uint4(hi[0], hi[1], lo[0], lo[1]);
    }
}

// util2: scatter coords -> idx_map + prep w3 B-fragments (first 4096)
__global__ void util2_kernel(const int* __restrict__ coords,
                             const float* __restrict__ w3, int n) {
    int i = blockIdx.x * blockDim.x + threadIdx.x;
    if (i < n) {
        int is64 = coords_is64(coords);
        g_idx_map[load_coord(coords, is64, i)] = i;
    }
    if (i < 4 * 4 * 8 * 32) {
        int lane = i & 31, nt = (i >> 5) & 7, kc = (i >> 8) & 3, cb = i >> 10;
        int nn = cb * 64 + nt * 8 + (lane >> 2);
        int k0 = kc * 16 + (lane & 3) * 2;
        uint32_t hi[2], lo[2];
#pragma unroll
        for (int j = 0; j < 2; ++j) {
            int k = k0 + j * 8;
            bsplit2(w3[k * 256 + nn], w3[(k + 1) * 256 + nn], hi[j], lo[j]);
        }
        g_w3f[i] = make_uint4(hi[0], hi[1], lo[0], lo[1]);
    }
}

// ---------------------------------------------------------------------------
// FFMA micro-kernel (conv1)
template <int LDA>
__device__ __forceinline__ void mm32(const float* __restrict__ sA,
                                     const float* __restrict__ sB,
                                     int trow, int tcol, float acc[8][4]) {
#pragma unroll
    for (int k = 0; k < 32; ++k) {
        float4 b = *(const float4*)(sB + k * 64 + tcol);
#pragma unroll
        for (int i = 0; i < 8; ++i) {
            float a = sA[(trow + i) * LDA + k];
            acc[i][0] = fmaf(a, b.x, acc[i][0]);
            acc[i][1] = fmaf(a, b.y, acc[i][1]);
            acc[i][2] = fmaf(a, b.z, acc[i][2]);
            acc[i][3] = fmaf(a, b.w, acc[i][3]);
        }
    }
}

// conv1: h1 = relu((feats @ w1) * s1 + b1) -> bf16 hi/lo planes  (R5 version)
__global__ void __launch_bounds__(256) conv1_kernel(
    const float* __restrict__ feats, const float* __restrict__ w1,
    const float* __restrict__ s1, const float* __restrict__ b1, int n)
{
    __shared__ __align__(16) float sA[128 * 33];
    __shared__ __align__(16) float sB[32 * 64];
    const int tid = threadIdx.x;
    const int site0 = blockIdx.x * 128;
    const int trow = (tid >> 4) << 3;
    const int tcol = (tid & 15) << 2;

    float acc[8][4];
#pragma unroll
    for (int i = 0; i < 8; ++i)
#pragma unroll
        for (int j = 0; j < 4; ++j) acc[i][j] = 0.f;

#pragma unroll 1
    for (int k0 = 0; k0 < 256; k0 += 32) {
#pragma unroll
        for (int l = 0; l < 4; ++l) {
            int i = tid + l * 256;
            int r = i >> 3, c4 = (i & 7) << 2;
            int site = site0 + r;
            float4 v = make_float4(0.f, 0.f, 0.f, 0.f);
            if (site < n) v = *(const float4*)&feats[(size_t)site * 256 + k0 + c4];
            sA[r * 33 + c4 + 0] = v.x; sA[r * 33 + c4 + 1] = v.y;
            sA[r * 33 + c4 + 2] = v.z; sA[r * 33 + c4 + 3] = v.w;
        }
#pragma unroll
        for (int l = 0; l < 2; ++l) {
            int i = tid + l * 256;
            int r = i >> 4, c4 = (i & 15) << 2;
            *(float4*)&sB[r * 64 + c4] = *(const float4*)&w1[(size_t)(k0 + r) * 64 + c4];
        }
        __syncthreads();
        mm32<33>(sA, sB, trow, tcol, acc);
        __syncthreads();
    }

    float sc[4], bi[4];
#pragma unroll
    for (int j = 0; j < 4; ++j) { sc[j] = s1[tcol + j]; bi[j] = b1[tcol + j]; }
#pragma unroll
    for (int i = 0; i < 8; ++i) {
        int site = site0 + trow + i;   // < NMAX always; OOB rows never read back
        float v0 = fmaxf(fmaf(acc[i][0], sc[0], bi[0]), 0.f);
        float v1 = fmaxf(fmaf(acc[i][1], sc[1], bi[1]), 0.f);
        float v2 = fmaxf(fmaf(acc[i][2], sc[2], bi[2]), 0.f);
        float v3 = fmaxf(fmaf(acc[i][3], sc[3], bi[3]), 0.f);
        uint32_t h0, l0, h1v, l1v;
        bsplit2(v0, v1, h0, l0);
        bsplit2(v2, v3, h1v, l1v);
        unsigned char* row = g_h1b + (size_t)site * 256;
        *(uint2*)(row + tcol * 2)       = make_uint2(h0, h1v);   // hi plane
        *(uint2*)(row + 128 + tcol * 2) = make_uint2(l0, l1v);   // lo plane
    }
}

// ---------------------------------------------------------------------------
// FUSED conv2 + conv3. Double-buffered cp.async.cg (L1-bypass) for both the
// A gather and the B-fragment stage; coalesced 16-lanes-per-256B-row mapping.
#define APL 18432                      // one plane: 128 rows * 144B
#define ABF (2 * APL)                  // A buffer (hi+lo planes) = 36864
#define LDP 144
// dynamic smem layout (bytes):
#define SM_SC    0                     // 640 floats = 2560
#define SM_NBR   2560                  // 9*128*4 = 4608 -> ends 7168
#define SM_A     7680                  // 2 buffers * ABF = 73728 -> ends 81408
#define SM_B     81408                 // 2 buffers * 16384 = 32768 -> ends 114176
#define SM_TOTAL 114176                // ~111.5KB per CTA (2 CTAs/SM)

__global__ void __launch_bounds__(256) conv23_kernel(
    const int* __restrict__ coords,
    const float* __restrict__ s2, const float* __restrict__ b2,
    const float* __restrict__ feats,
    const float* __restrict__ s3, const float* __restrict__ b3,
    float* __restrict__ out, int n)
{
    extern __shared__ __align__(128) char dsm[];
    float* s_s2 = (float*)(dsm + SM_SC);
    float* s_b2 = s_s2 + 64;
    float* s_s3 = s_b2 + 64;
    float* s_b3 = s_s3 + 256;
    int*  s_nbr = (int*)(dsm + SM_NBR);
    unsigned char* Abuf = (unsigned char*)(dsm + SM_A);
    uint4* Bsm = (uint4*)(dsm + SM_B);

    const int tid = threadIdx.x, wid = tid >> 5, lane = tid & 31;
    const int site0 = blockIdx.x * 128;
    const int rw = wid * 16;

    // coalesced 256B-row mapping: 16 lanes cover one row
    const int sub  = lane >> 4;          // row of the pair
    const int boff = (lane & 15) * 16;   // byte chunk within 256B row
    const int psel = boff >> 7;          // 0 = hi plane, 1 = lo plane
    const int poff = boff & 127;         // byte within plane row

    if (tid < 64) { s_s2[tid] = s2[tid]; s_b2[tid] = b2[tid]; }
    s_s3[tid] = s3[tid]; s_b3[tid] = b3[tid];
    if (tid < 128) {
#pragma unroll
        for (int t = 0; t < 9; ++t) s_nbr[t * 128 + tid] = -1;
        int site = site0 + tid;
        if (site < n) {
            int is64 = coords_is64(coords);
            int c = load_coord(coords, is64, site);
            int y = c / WGRID, x = c % WGRID;
#pragma unroll
            for (int t = 0; t < 9; ++t) {
                int ny = y + t / 3 - 1, nx = x + t % 3 - 1;
                if (ny >= 0 && ny < HGRID && nx >= 0 && nx < WGRID)
                    s_nbr[t * 128 + tid] = g_idx_map[ny * WGRID + nx];
            }
        }
    }
    __syncthreads();   // nbr table ready before any gather issue

    float acc[8][4];
#pragma unroll
    for (int t = 0; t < 8; ++t)
#pragma unroll
        for (int j = 0; j < 4; ++j) acc[t][j] = 0.f;

    const uint32_t a_sm = smem_u32(Abuf);
    const uint32_t b_sm = smem_u32(Bsm);

    // issue tap t's A gather + B stage into buffer (t&1), one commit group
    auto issue_tap = [&](int t) {
        uint32_t abase = a_sm + (t & 1) * ABF + psel * APL + poff;
#pragma unroll
        for (int g = 0; g < 8; ++g) {
            int row = rw + g * 2 + sub;
            int nb = s_nbr[t * 128 + row];
            const unsigned char* src = g_h1b + (size_t)(nb < 0 ? 0 : nb) * 256 + boff;
            cp_async16_cg(abase + row * LDP, src, nb >= 0 ? 16 : 0);
        }
        const uint4* bs = g_w2f + (size_t)t * 1024 + tid * 4;
        uint32_t bd = b_sm + (t & 1) * 16384 + tid * 64;
#pragma unroll
        for (int q = 0; q < 4; ++q) cp_async16_cg(bd + q * 16, bs + q, 16);
        CP_COMMIT();
    };

    issue_tap(0);   // prologue

    // ---------------- conv2: 9-tap sparse 3x3 accumulation ----------------
#pragma unroll 1
    for (int tap = 0; tap < 9; ++tap) {
        CP_WAIT0();                  // tap's data landed
        __syncthreads();             // all warps done reading buffer (tap-1)&1
        if (tap < 8) issue_tap(tap + 1);   // retires under the MMAs below

        const unsigned char* wbase = Abuf + (tap & 1) * ABF;
        const uint4* Bcur = Bsm + (tap & 1) * 1024;
#pragma unroll
        for (int kc = 0; kc < 4; ++kc) {
            uint32_t ab = (uint32_t)((rw + (lane >> 2)) * LDP + kc * 32 + (lane & 3) * 4);
            uint32_t ah[4], al[4];
            ah[0] = *(const uint32_t*)(wbase + ab);
            ah[1] = *(const uint32_t*)(wbase + ab + 8 * LDP);
            ah[2] = *(const uint32_t*)(wbase + ab + 16);
            ah[3] = *(const uint32_t*)(wbase + ab + 8 * LDP + 16);
            al[0] = *(const uint32_t*)(wbase + APL + ab);
            al[1] = *(const uint32_t*)(wbase + APL + ab + 8 * LDP);
            al[2] = *(const uint32_t*)(wbase + APL + ab + 16);
            al[3] = *(const uint32_t*)(wbase + APL + ab + 8 * LDP + 16);
#pragma unroll
            for (int nt = 0; nt < 8; ++nt) {
                uint4 b = Bcur[kc * 256 + nt * 32 + lane];
                mma16816(acc[nt], ah, b.x, b.y);
                mma16816(acc[nt], ah, b.z, b.w);
                mma16816(acc[nt], al, b.x, b.y);
            }
        }
    }
    __syncthreads();   // RACE FIX: all warps finish MMA(tap 8) reads of
                       // Abuf buf0 / Bsm buf0 before conv3 reuses them.

    // ------- bn2 + relu in registers; repackage C-frags as A-frags --------
    uint32_t fh[4][4], fl[4][4];
    {
        const int n0 = (lane & 3) * 2;
#pragma unroll
        for (int kc = 0; kc < 4; ++kc) {
#pragma unroll
            for (int q = 0; q < 2; ++q) {
                int nt = 2 * kc + q;
                int c0 = nt * 8 + n0;
                float v0 = fmaxf(fmaf(acc[nt][0], s_s2[c0],     s_b2[c0]),     0.f);
                float v1 = fmaxf(fmaf(acc[nt][1], s_s2[c0 + 1], s_b2[c0 + 1]), 0.f);
                float v2 = fmaxf(fmaf(acc[nt][2], s_s2[c0],     s_b2[c0]),     0.f);
                float v3 = fmaxf(fmaf(acc[nt][3], s_s2[c0 + 1], s_b2[c0 + 1]), 0.f);
                bsplit2(v0, v1, fh[kc][2 * q],     fl[kc][2 * q]);
                bsplit2(v2, v3, fh[kc][2 * q + 1], fl[kc][2 * q + 1]);
            }
        }
    }

    // ---------------- conv3: 4 column blocks of 64, from registers --------
    float* stg = (float*)Abuf;   // 128 x 64 f32 staging = 32KB (fits buffer 0)
    {   // preload cb=0 B fragments (plain LDG+STS, off critical path)
        const uint4* bs = g_w3f + tid * 4;
#pragma unroll
        for (int q = 0; q < 4; ++q) Bsm[tid * 4 + q] = bs[q];
    }
    __syncthreads();

#pragma unroll 1
    for (int cb = 0; cb < 4; ++cb) {
        float acc2[8][4];
#pragma unroll
        for (int t = 0; t < 8; ++t)
#pragma unroll
            for (int j = 0; j < 4; ++j) acc2[t][j] = 0.f;

#pragma unroll
        for (int kc = 0; kc < 4; ++kc) {
#pragma unroll
            for (int nt = 0; nt < 8; ++nt) {
                uint4 b = Bsm[kc * 256 + nt * 32 + lane];
                mma16816(acc2[nt], fh[kc], b.x, b.y);
                mma16816(acc2[nt], fh[kc], b.z, b.w);
                mma16816(acc2[nt], fl[kc], b.x, b.y);
            }
        }
        __syncthreads();   // B reads done; stg free (prev write-out done)
        {
            int r0 = rw + (lane >> 2);
            int n0 = (lane & 3) * 2;
#pragma unroll
            for (int nt = 0; nt < 8; ++nt) {
                int c  = nt * 8 + n0;
                int cg = cb * 64 + c;
                stg[r0 * 64 + c]           = fmaf(acc2[nt][0], s_s3[cg],     s_b3[cg]);
                stg[r0 * 64 + c + 1]       = fmaf(acc2[nt][1], s_s3[cg + 1], s_b3[cg + 1]);
                stg[(r0 + 8) * 64 + c]     = fmaf(acc2[nt][2], s_s3[cg],     s_b3[cg]);
                stg[(r0 + 8) * 64 + c + 1] = fmaf(acc2[nt][3], s_s3[cg + 1], s_b3[cg + 1]);
            }
        }
        if (cb < 3) {   // stage next cb's B fragments
            const uint4* bs = g_w3f + (size_t)(cb + 1) * 1024 + tid * 4;
#pragma unroll
            for (int q = 0; q < 4; ++q) Bsm[tid * 4 + q] = bs[q];
        }
        __syncthreads();   // stg + next B visible
        {   // coalesced residual+relu+write: 2 sites per instr, 4 lines
#pragma unroll
            for (int g = 0; g < 8; ++g) {
                int row = rw + g * 2 + sub;
                int site = site0 + row;
                if (site < n) {
                    float4 a = *(const float4*)((const char*)stg + row * 256 + boff);
                    float4 b = *(const float4*)((const char*)feats +
                                                (size_t)site * 1024 + cb * 256 + boff);
                    float4 o;
                    o.x = fmaxf(a.x + b.x, 0.f);
                    o.y = fmaxf(a.y + b.y, 0.f);
                    o.z = fmaxf(a.z + b.z, 0.f);
                    o.w = fmaxf(a.w + b.w, 0.f);
                    *(float4*)((char*)out + (size_t)site * 1024 + cb * 256 + boff) = o;
                }
            }
        }
    }
}

// ---------------------------------------------------------------------------
extern "C" void kernel_launch(void* const* d_in, const int* in_sizes, int n_in,
                              void* d_out, int out_size) {
    const float* feats  = (const float*)d_in[0];
    const int*   coords = (const int*)d_in[1];
    const float* w1     = (const float*)d_in[2];
    const float* w2     = (const float*)d_in[3];
    const float* w3     = (const float*)d_in[4];
    const float* s1     = (const float*)d_in[5];
    const float* b1     = (const float*)d_in[6];
    const float* s2     = (const float*)d_in[7];
    const float* b2     = (const float*)d_in[8];
    const float* s3     = (const float*)d_in[9];
    const float* b3     = (const float*)d_in[10];
    float* out = (float*)d_out;

    const int n = in_sizes[0] / 256;
    const int tiles = (n + 127) / 128;

    cudaFuncSetAttribute(conv23_kernel,
                         cudaFuncAttributeMaxDynamicSharedMemorySize, SM_TOTAL);

    // 4 launches; conv23 is launch #4 so ncu (-s/-c window) captures it.
    util1_kernel<<<(HGRID * WGRID + 255) / 256, 256>>>(w2);                 // #1
    util2_kernel<<<(max(n, 4096) + 255) / 256, 256>>>(coords, w3, n);       // #2
    conv1_kernel<<<tiles, 256>>>(feats, w1, s1, b1, n);                     // #3
    conv23_kernel<<<tiles, 256, SM_TOTAL>>>(coords, s2, b2, feats, s3, b3, out, n);  // #4
}

// round 13
// speedup vs baseline: 2.0584x; 1.2000x over previous
#include <cuda_runtime.h>
#include <cuda_bf16.h>
#include <cstdint>

#define HGRID 768
#define WGRID 768
#define NMAX  200064   // 1563 * 128

// Scratch in __device__ globals (no allocation allowed).
__device__ int g_idx_map[HGRID * WGRID];
// h1 as interleaved bf16 split planes: per row {128B hi, 128B lo}
__device__ __align__(16) unsigned char g_h1b[(size_t)NMAX * 256];
// B fragments (uint4 = {bhi0,bhi1,blo0,blo1}):
__device__ uint4 g_w1f[16 * 8 * 32];      // w1: [kc(16)][nt(8)][lane(32)]
__device__ uint4 g_w2f[9 * 4 * 8 * 32];   // w2: [tap][kc(4)][nt(8)][lane(32)]
__device__ uint4 g_w3f[4 * 4 * 8 * 32];   // w3: [cb(4)][kc(4)][nt(8)][lane(32)]

// ---------------------------------------------------------------------------
__device__ __forceinline__ int coords_is64(const int* c) { return c[1] == 0; }
__device__ __forceinline__ int load_coord(const int* c, int is64, int i) {
    return is64 ? c[2 * i] : c[i];
}
__device__ __forceinline__ void bsplit2(float a, float b, uint32_t& hi, uint32_t& lo) {
    __nv_bfloat16 ah = __float2bfloat16(a);
    __nv_bfloat16 bh = __float2bfloat16(b);
    float ar = a - __bfloat162float(ah);
    float br = b - __bfloat162float(bh);
    __nv_bfloat162 h; h.x = ah; h.y = bh;
    __nv_bfloat162 l; l.x = __float2bfloat16(ar); l.y = __float2bfloat16(br);
    hi = *reinterpret_cast<uint32_t*>(&h);
    lo = *reinterpret_cast<uint32_t*>(&l);
}
__device__ __forceinline__ uint32_t smem_u32(const void* p) {
    uint32_t a;
    asm("{ .reg .u64 t; cvta.to.shared.u64 t, %1; cvt.u32.u64 %0, t; }"
        : "=r"(a) : "l"(p));
    return a;
}
// L2-direct async copy (bypasses L1 -> no pollution of anything)
__device__ __forceinline__ void cp_async16_cg(uint32_t dst, const void* src, int srcsize) {
    asm volatile("cp.async.cg.shared.global [%0], [%1], 16, %2;"
                 :: "r"(dst), "l"(src), "r"(srcsize) : "memory");
}
#define CP_COMMIT() asm volatile("cp.async.commit_group;" ::: "memory")
#define CP_WAIT0()  asm volatile("cp.async.wait_group 0;" ::: "memory")

// mma.sync m16n8k16 bf16 -> f32 accumulate
__device__ __forceinline__ void mma16816(float c[4], const uint32_t a[4],
                                         uint32_t b0, uint32_t b1) {
    asm volatile(
        "mma.sync.aligned.m16n8k16.row.col.f32.bf16.bf16.f32 "
        "{%0,%1,%2,%3}, {%4,%5,%6,%7}, {%8,%9}, {%0,%1,%2,%3};"
        : "+f"(c[0]), "+f"(c[1]), "+f"(c[2]), "+f"(c[3])
        : "r"(a[0]), "r"(a[1]), "r"(a[2]), "r"(a[3]), "r"(b0), "r"(b1));
}

// ---------------------------------------------------------------------------
// util1: clear idx_map (all threads) + prep w2 B-fragments (first 9216)
__global__ void util1_kernel(const float* __restrict__ w2) {
    int i = blockIdx.x * blockDim.x + threadIdx.x;
    if (i < HGRID * WGRID) g_idx_map[i] = -1;
    if (i < 9 * 4 * 8 * 32) {
        int lane = i & 31, nt = (i >> 5) & 7, kc = (i >> 8) & 3, tap = i >> 10;
        int n  = nt * 8 + (lane >> 2);
        int k0 = kc * 16 + (lane & 3) * 2;
        uint32_t hi[2], lo[2];
#pragma unroll
        for (int j = 0; j < 2; ++j) {
            int k = k0 + j * 8;
            bsplit2(w2[tap * 4096 + k * 64 + n], w2[tap * 4096 + (k + 1) * 64 + n],
                    hi[j], lo[j]);
        }
        g_w2f[i] = make_uint4(hi[0], hi[1], lo[0], lo[1]);
    }
}

// util2: scatter coords + prep w3 B-fragments (i<4096) + w1 B-frags ([4096,8192))
__global__ void util2_kernel(const int* __restrict__ coords,
                             const float* __restrict__ w3,
                             const float* __restrict__ w1, int n) {
    int i = blockIdx.x * blockDim.x + threadIdx.x;
    if (i < n) {
        int is64 = coords_is64(coords);
        g_idx_map[load_coord(coords, is64, i)] = i;
    }
    if (i < 4 * 4 * 8 * 32) {
        int lane = i & 31, nt = (i >> 5) & 7, kc = (i >> 8) & 3, cb = i >> 10;
        int nn = cb * 64 + nt * 8 + (lane >> 2);
        int k0 = kc * 16 + (lane & 3) * 2;
        uint32_t hi[2], lo[2];
#pragma unroll
        for (int j = 0; j < 2; ++j) {
            int k = k0 + j * 8;
            bsplit2(w3[k * 256 + nn], w3[(k + 1) * 256 + nn], hi[j], lo[j]);
        }
        g_w3f[i] = make_uint4(hi[0], hi[1], lo[0], lo[1]);
    } else if (i < 8192) {
        int j = i - 4096;
        int lane = j & 31, nt = (j >> 5) & 7, kc = j >> 8;   // kc 0..15
        int nn = nt * 8 + (lane >> 2);
        int k0 = kc * 16 + (lane & 3) * 2;
        uint32_t hi[2], lo[2];
#pragma unroll
        for (int q = 0; q < 2; ++q) {
            int k = k0 + q * 8;
            bsplit2(w1[k * 64 + nn], w1[(k + 1) * 64 + nn], hi[q], lo[q]);
        }
        g_w1f[j] = make_uint4(hi[0], hi[1], lo[0], lo[1]);
    }
}

// ---------------------------------------------------------------------------
// conv1 via mma.sync (3-term bf16 split), cp.async.cg double-buffered feats
// chunks + staged w1 B-fragments; 54KB smem -> 3 CTAs/SM.
//   h1 = relu((feats @ w1) * s1 + b1) -> bf16 hi/lo planes in g_h1b
#define LDF 144                        // bytes per f32 chunk row (32 f32 + pad)
#define FPL (128 * LDF)                // 18432 per chunk buffer
#define S1_SC 0                        // s1,b1: 512B
#define S1_F  512                      // 2 * FPL -> ends 37376
#define S1_B  37376                    // 2 * 8192 -> ends 53760
#define S1_TOTAL 53760

__global__ void __launch_bounds__(256, 3) conv1_mma_kernel(
    const float* __restrict__ feats,
    const float* __restrict__ s1, const float* __restrict__ b1, int n)
{
    extern __shared__ __align__(128) char dsm1[];
    float* s_s1 = (float*)(dsm1 + S1_SC);
    float* s_b1 = s_s1 + 64;
    unsigned char* sF = (unsigned char*)(dsm1 + S1_F);
    uint4* Bsm = (uint4*)(dsm1 + S1_B);

    const int tid = threadIdx.x, wid = tid >> 5, lane = tid & 31;
    const int site0 = blockIdx.x * 128;
    const int rw = wid * 16;
    const int frow = tid >> 3, fc8 = tid & 7;   // feats loader: 8 lanes per 128B chunk-row

    if (tid < 64) { s_s1[tid] = s1[tid]; s_b1[tid] = b1[tid]; }

    const uint32_t f_sm = smem_u32(sF);
    const uint32_t b_sm = smem_u32(Bsm);

    // issue chunk ck (32 k-values: feats 16KB + w1f slice 8KB) into buffer ck&1
    auto issue_ck = [&](int ck) {
        uint32_t fdst = f_sm + (ck & 1) * FPL;
#pragma unroll
        for (int g = 0; g < 4; ++g) {
            int row = frow + g * 32;
            int site = site0 + row;
            const char* src = (const char*)feats +
                (size_t)(site < n ? site : 0) * 1024 + ck * 128 + fc8 * 16;
            cp_async16_cg(fdst + row * LDF + fc8 * 16, src, site < n ? 16 : 0);
        }
        const uint4* bs = g_w1f + (size_t)ck * 512 + tid * 2;
        uint32_t bd = b_sm + (ck & 1) * 8192 + tid * 32;
        cp_async16_cg(bd, bs, 16);
        cp_async16_cg(bd + 16, bs + 1, 16);
        CP_COMMIT();
    };

    float acc[8][4];
#pragma unroll
    for (int t = 0; t < 8; ++t)
#pragma unroll
        for (int j = 0; j < 4; ++j) acc[t][j] = 0.f;

    issue_ck(0);   // prologue

#pragma unroll 1
    for (int ck = 0; ck < 8; ++ck) {
        CP_WAIT0();
        __syncthreads();                 // chunk landed; prev buffer's readers done
        if (ck < 7) issue_ck(ck + 1);    // retires under the MMAs below

        const unsigned char* fb = sF + (ck & 1) * FPL;
        const uint4* Bcur = Bsm + (ck & 1) * 512;
#pragma unroll
        for (int kh = 0; kh < 2; ++kh) {
            uint32_t ab = (uint32_t)((rw + (lane >> 2)) * LDF + kh * 64 + (lane & 3) * 8);
            float2 p00 = *(const float2*)(fb + ab);
            float2 p10 = *(const float2*)(fb + ab + 8 * LDF);
            float2 p01 = *(const float2*)(fb + ab + 32);
            float2 p11 = *(const float2*)(fb + ab + 8 * LDF + 32);
            uint32_t ah[4], al[4];
            bsplit2(p00.x, p00.y, ah[0], al[0]);
            bsplit2(p10.x, p10.y, ah[1], al[1]);
            bsplit2(p01.x, p01.y, ah[2], al[2]);
            bsplit2(p11.x, p11.y, ah[3], al[3]);
#pragma unroll
            for (int nt = 0; nt < 8; ++nt) {
                uint4 b = Bcur[kh * 256 + nt * 32 + lane];
                mma16816(acc[nt], ah, b.x, b.y);
                mma16816(acc[nt], ah, b.z, b.w);
                mma16816(acc[nt], al, b.x, b.y);
            }
        }
    }
    __syncthreads();   // all MMA reads done before sF reuse as staging

    // epilogue: bn1 + relu, bf16 split, stage rows {128B hi,128B lo}, write
    uint32_t* sh = (uint32_t*)sF;   // row stride 64 words = 256B
    {
        int r0 = rw + (lane >> 2);
        int n0 = (lane & 3) * 2;
#pragma unroll
        for (int nt = 0; nt < 8; ++nt) {
            int c0 = nt * 8 + n0;
            int wc = nt * 4 + (lane & 3);
            float v0 = fmaxf(fmaf(acc[nt][0], s_s1[c0],     s_b1[c0]),     0.f);
            float v1 = fmaxf(fmaf(acc[nt][1], s_s1[c0 + 1], s_b1[c0 + 1]), 0.f);
            float v2 = fmaxf(fmaf(acc[nt][2], s_s1[c0],     s_b1[c0]),     0.f);
            float v3 = fmaxf(fmaf(acc[nt][3], s_s1[c0 + 1], s_b1[c0 + 1]), 0.f);
            uint32_t h, l;
            bsplit2(v0, v1, h, l);
            sh[r0 * 64 + wc] = h; sh[r0 * 64 + 32 + wc] = l;
            bsplit2(v2, v3, h, l);
            sh[(r0 + 8) * 64 + wc] = h; sh[(r0 + 8) * 64 + 32 + wc] = l;
        }
    }
    __syncthreads();
    {   // coalesced write-out: 16 lanes per 256B row, 16 rows per pass
        int chunk = tid & 15, rbase = tid >> 4;
#pragma unroll
        for (int it = 0; it < 8; ++it) {
            int row = rbase + it * 16;
            uint4 v = *(const uint4*)((const char*)sh + row * 256 + chunk * 16);
            *(uint4*)(g_h1b + (size_t)(site0 + row) * 256 + chunk * 16) = v;
        }
    }
}

// ---------------------------------------------------------------------------
// FUSED conv2 + conv3 (R12, unchanged). Double-buffered cp.async.cg for A
// gather + B-fragment stage; coalesced 16-lanes-per-256B-row mapping.
#define APL 18432                      // one plane: 128 rows * 144B
#define ABF (2 * APL)                  // A buffer (hi+lo planes) = 36864
#define LDP 144
#define SM_SC    0
#define SM_NBR   2560
#define SM_A     7680
#define SM_B     81408
#define SM_TOTAL 114176

__global__ void __launch_bounds__(256) conv23_kernel(
    const int* __restrict__ coords,
    const float* __restrict__ s2, const float* __restrict__ b2,
    const float* __restrict__ feats,
    const float* __restrict__ s3, const float* __restrict__ b3,
    float* __restrict__ out, int n)
{
    extern __shared__ __align__(128) char dsm[];
    float* s_s2 = (float*)(dsm + SM_SC);
    float* s_b2 = s_s2 + 64;
    float* s_s3 = s_b2 + 64;
    float* s_b3 = s_s3 + 256;
    int*  s_nbr = (int*)(dsm + SM_NBR);
    unsigned char* Abuf = (unsigned char*)(dsm + SM_A);
    uint4* Bsm = (uint4*)(dsm + SM_B);

    const int tid = threadIdx.x, wid = tid >> 5, lane = tid & 31;
    const int site0 = blockIdx.x * 128;
    const int rw = wid * 16;

    const int sub  = lane >> 4;
    const int boff = (lane & 15) * 16;
    const int psel = boff >> 7;
    const int poff = boff & 127;

    if (tid < 64) { s_s2[tid] = s2[tid]; s_b2[tid] = b2[tid]; }
    s_s3[tid] = s3[tid]; s_b3[tid] = b3[tid];
    if (tid < 128) {
#pragma unroll
        for (int t = 0; t < 9; ++t) s_nbr[t * 128 + tid] = -1;
        int site = site0 + tid;
        if (site < n) {
            int is64 = coords_is64(coords);
            int c = load_coord(coords, is64, site);
            int y = c / WGRID, x = c % WGRID;
#pragma unroll
            for (int t = 0; t < 9; ++t) {
                int ny = y + t / 3 - 1, nx = x + t % 3 - 1;
                if (ny >= 0 && ny < HGRID && nx >= 0 && nx < WGRID)
                    s_nbr[t * 128 + tid] = g_idx_map[ny * WGRID + nx];
            }
        }
    }
    __syncthreads();

    float acc[8][4];
#pragma unroll
    for (int t = 0; t < 8; ++t)
#pragma unroll
        for (int j = 0; j < 4; ++j) acc[t][j] = 0.f;

    const uint32_t a_sm = smem_u32(Abuf);
    const uint32_t b_sm = smem_u32(Bsm);

    auto issue_tap = [&](int t) {
        uint32_t abase = a_sm + (t & 1) * ABF + psel * APL + poff;
#pragma unroll
        for (int g = 0; g < 8; ++g) {
            int row = rw + g * 2 + sub;
            int nb = s_nbr[t * 128 + row];
            const unsigned char* src = g_h1b + (size_t)(nb < 0 ? 0 : nb) * 256 + boff;
            cp_async16_cg(abase + row * LDP, src, nb >= 0 ? 16 : 0);
        }
        const uint4* bs = g_w2f + (size_t)t * 1024 + tid * 4;
        uint32_t bd = b_sm + (t & 1) * 16384 + tid * 64;
#pragma unroll
        for (int q = 0; q < 4; ++q) cp_async16_cg(bd + q * 16, bs + q, 16);
        CP_COMMIT();
    };

    issue_tap(0);

#pragma unroll 1
    for (int tap = 0; tap < 9; ++tap) {
        CP_WAIT0();
        __syncthreads();
        if (tap < 8) issue_tap(tap + 1);

        const unsigned char* wbase = Abuf + (tap & 1) * ABF;
        const uint4* Bcur = Bsm + (tap & 1) * 1024;
#pragma unroll
        for (int kc = 0; kc < 4; ++kc) {
            uint32_t ab = (uint32_t)((rw + (lane >> 2)) * LDP + kc * 32 + (lane & 3) * 4);
            uint32_t ah[4], al[4];
            ah[0] = *(const uint32_t*)(wbase + ab);
            ah[1] = *(const uint32_t*)(wbase + ab + 8 * LDP);
            ah[2] = *(const uint32_t*)(wbase + ab + 16);
            ah[3] = *(const uint32_t*)(wbase + ab + 8 * LDP + 16);
            al[0] = *(const uint32_t*)(wbase + APL + ab);
            al[1] = *(const uint32_t*)(wbase + APL + ab + 8 * LDP);
            al[2] = *(const uint32_t*)(wbase + APL + ab + 16);
            al[3] = *(const uint32_t*)(wbase + APL + ab + 8 * LDP + 16);
#pragma unroll
            for (int nt = 0; nt < 8; ++nt) {
                uint4 b = Bcur[kc * 256 + nt * 32 + lane];
                mma16816(acc[nt], ah, b.x, b.y);
                mma16816(acc[nt], ah, b.z, b.w);
                mma16816(acc[nt], al, b.x, b.y);
            }
        }
    }
    __syncthreads();   // all warps finish MMA(tap 8) before buffer reuse

    uint32_t fh[4][4], fl[4][4];
    {
        const int n0 = (lane & 3) * 2;
#pragma unroll
        for (int kc = 0; kc < 4; ++kc) {
#pragma unroll
            for (int q = 0; q < 2; ++q) {
                int nt = 2 * kc + q;
                int c0 = nt * 8 + n0;
                float v0 = fmaxf(fmaf(acc[nt][0], s_s2[c0],     s_b2[c0]),     0.f);
                float v1 = fmaxf(fmaf(acc[nt][1], s_s2[c0 + 1], s_b2[c0 + 1]), 0.f);
                float v2 = fmaxf(fmaf(acc[nt][2], s_s2[c0],     s_b2[c0]),     0.f);
                float v3 = fmaxf(fmaf(acc[nt][3], s_s2[c0 + 1], s_b2[c0 + 1]), 0.f);
                bsplit2(v0, v1, fh[kc][2 * q],     fl[kc][2 * q]);
                bsplit2(v2, v3, fh[kc][2 * q + 1], fl[kc][2 * q + 1]);
            }
        }
    }

    float* stg = (float*)Abuf;
    {
        const uint4* bs = g_w3f + tid * 4;
#pragma unroll
        for (int q = 0; q < 4; ++q) Bsm[tid * 4 + q] = bs[q];
    }
    __syncthreads();

#pragma unroll 1
    for (int cb = 0; cb < 4; ++cb) {
        float acc2[8][4];
#pragma unroll
        for (int t = 0; t < 8; ++t)
#pragma unroll
            for (int j = 0; j < 4; ++j) acc2[t][j] = 0.f;

#pragma unroll
        for (int kc = 0; kc < 4; ++kc) {
#pragma unroll
            for (int nt = 0; nt < 8; ++nt) {
                uint4 b = Bsm[kc * 256 + nt * 32 + lane];
                mma16816(acc2[nt], fh[kc], b.x, b.y);
                mma16816(acc2[nt], fh[kc], b.z, b.w);
                mma16816(acc2[nt], fl[kc], b.x, b.y);
            }
        }
        __syncthreads();
        {
            int r0 = rw + (lane >> 2);
            int n0 = (lane & 3) * 2;
#pragma unroll
            for (int nt = 0; nt < 8; ++nt) {
                int c  = nt * 8 + n0;
                int cg = cb * 64 + c;
                stg[r0 * 64 + c]           = fmaf(acc2[nt][0], s_s3[cg],     s_b3[cg]);
                stg[r0 * 64 + c + 1]       = fmaf(acc2[nt][1], s_s3[cg + 1], s_b3[cg + 1]);
                stg[(r0 + 8) * 64 + c]     = fmaf(acc2[nt][2], s_s3[cg],     s_b3[cg]);
                stg[(r0 + 8) * 64 + c + 1] = fmaf(acc2[nt][3], s_s3[cg + 1], s_b3[cg + 1]);
            }
        }
        if (cb < 3) {
            const uint4* bs = g_w3f + (size_t)(cb + 1) * 1024 + tid * 4;
#pragma unroll
            for (int q = 0; q < 4; ++q) Bsm[tid * 4 + q] = bs[q];
        }
        __syncthreads();
        {
#pragma unroll
            for (int g = 0; g < 8; ++g) {
                int row = rw + g * 2 + sub;
                int site = site0 + row;
                if (site < n) {
                    float4 a = *(const float4*)((const char*)stg + row * 256 + boff);
                    float4 b = *(const float4*)((const char*)feats +
                                                (size_t)site * 1024 + cb * 256 + boff);
                    float4 o;
                    o.x = fmaxf(a.x + b.x, 0.f);
                    o.y = fmaxf(a.y + b.y, 0.f);
                    o.z = fmaxf(a.z + b.z, 0.f);
                    o.w = fmaxf(a.w + b.w, 0.f);
                    *(float4*)((char*)out + (size_t)site * 1024 + cb * 256 + boff) = o;
                }
            }
        }
    }
}

// ---------------------------------------------------------------------------
extern "C" void kernel_launch(void* const* d_in, const int* in_sizes, int n_in,
                              void* d_out, int out_size) {
    const float* feats  = (const float*)d_in[0];
    const int*   coords = (const int*)d_in[1];
    const float* w1     = (const float*)d_in[2];
    const float* w2     = (const float*)d_in[3];
    const float* w3     = (const float*)d_in[4];
    const float* s1     = (const float*)d_in[5];
    const float* b1     = (const float*)d_in[6];
    const float* s2     = (const float*)d_in[7];
    const float* b2     = (const float*)d_in[8];
    const float* s3     = (const float*)d_in[9];
    const float* b3     = (const float*)d_in[10];
    float* out = (float*)d_out;

    const int n = in_sizes[0] / 256;
    const int tiles = (n + 127) / 128;

    cudaFuncSetAttribute(conv1_mma_kernel,
                         cudaFuncAttributeMaxDynamicSharedMemorySize, S1_TOTAL);
    cudaFuncSetAttribute(conv23_kernel,
                         cudaFuncAttributeMaxDynamicSharedMemorySize, SM_TOTAL);

    // 4 launches; conv23 is launch #4 so ncu (-s/-c window) captures it.
    util1_kernel<<<(HGRID * WGRID + 255) / 256, 256>>>(w2);                   // #1
    util2_kernel<<<(max(n, 8192) + 255) / 256, 256>>>(coords, w3, w1, n);     // #2
    conv1_mma_kernel<<<tiles, 256, S1_TOTAL>>>(feats, s1, b1, n);             // #3
    conv23_kernel<<<tiles, 256, SM_TOTAL>>>(coords, s2, b2, feats, s3, b3, out, n);  // #4
}

// round 14
// speedup vs baseline: 2.2386x; 1.0875x over previous
#include <cuda_runtime.h>
#include <cuda_bf16.h>
#include <cuda_fp16.h>
#include <cstdint>

#define HGRID 768
#define WGRID 768
#define NMAX  200064   // 1563 * 128

// Scratch in __device__ globals (no allocation allowed).
__device__ int g_idx_map[HGRID * WGRID];
// h1 as interleaved fp16 split planes: per row {128B hi, 128B lo}
__device__ __align__(16) unsigned char g_h1b[(size_t)NMAX * 256];
// Weight fragments:
__device__ uint4 g_w1f[16 * 8 * 32];      // w1 bf16 3-term: [kc(16)][nt(8)][lane]
__device__ uint2 g_w2h[9 * 4 * 8 * 32];   // w2 fp16 Bh-only: [tap][kc][nt][lane]
__device__ uint4 g_w3f[4 * 4 * 8 * 32];   // w3 bf16 3-term: [cb][kc][nt][lane]

// ---------------------------------------------------------------------------
__device__ __forceinline__ int coords_is64(const int* c) { return c[1] == 0; }
__device__ __forceinline__ int load_coord(const int* c, int is64, int i) {
    return is64 ? c[2 * i] : c[i];
}
__device__ __forceinline__ void bsplit2(float a, float b, uint32_t& hi, uint32_t& lo) {
    __nv_bfloat16 ah = __float2bfloat16(a);
    __nv_bfloat16 bh = __float2bfloat16(b);
    float ar = a - __bfloat162float(ah);
    float br = b - __bfloat162float(bh);
    __nv_bfloat162 h; h.x = ah; h.y = bh;
    __nv_bfloat162 l; l.x = __float2bfloat16(ar); l.y = __float2bfloat16(br);
    hi = *reinterpret_cast<uint32_t*>(&h);
    lo = *reinterpret_cast<uint32_t*>(&l);
}
// fp16 exact split: a = hi + lo to ~2^-22
__device__ __forceinline__ void hsplit2(float a, float b, uint32_t& hi, uint32_t& lo) {
    __half ah = __float2half_rn(a);
    __half bh = __float2half_rn(b);
    float ar = a - __half2float(ah);
    float br = b - __half2float(bh);
    __half2 h; h.x = ah; h.y = bh;
    __half2 l; l.x = __float2half_rn(ar); l.y = __float2half_rn(br);
    hi = *reinterpret_cast<uint32_t*>(&h);
    lo = *reinterpret_cast<uint32_t*>(&l);
}
__device__ __forceinline__ uint32_t pack_h2(float a, float b) {
    __half2 h; h.x = __float2half_rn(a); h.y = __float2half_rn(b);
    return *reinterpret_cast<uint32_t*>(&h);
}
__device__ __forceinline__ uint32_t smem_u32(const void* p) {
    uint32_t a;
    asm("{ .reg .u64 t; cvta.to.shared.u64 t, %1; cvt.u32.u64 %0, t; }"
        : "=r"(a) : "l"(p));
    return a;
}
// L2-direct async copy (bypasses L1)
__device__ __forceinline__ void cp_async16_cg(uint32_t dst, const void* src, int srcsize) {
    asm volatile("cp.async.cg.shared.global [%0], [%1], 16, %2;"
                 :: "r"(dst), "l"(src), "r"(srcsize) : "memory");
}
#define CP_COMMIT() asm volatile("cp.async.commit_group;" ::: "memory")
#define CP_WAIT0()  asm volatile("cp.async.wait_group 0;" ::: "memory")

// mma.sync m16n8k16 bf16 -> f32 accumulate
__device__ __forceinline__ void mma16816(float c[4], const uint32_t a[4],
                                         uint32_t b0, uint32_t b1) {
    asm volatile(
        "mma.sync.aligned.m16n8k16.row.col.f32.bf16.bf16.f32 "
        "{%0,%1,%2,%3}, {%4,%5,%6,%7}, {%8,%9}, {%0,%1,%2,%3};"
        : "+f"(c[0]), "+f"(c[1]), "+f"(c[2]), "+f"(c[3])
        : "r"(a[0]), "r"(a[1]), "r"(a[2]), "r"(a[3]), "r"(b0), "r"(b1));
}
// mma.sync m16n8k16 fp16 -> f32 accumulate
__device__ __forceinline__ void mma16816h(float c[4], const uint32_t a[4],
                                          uint32_t b0, uint32_t b1) {
    asm volatile(
        "mma.sync.aligned.m16n8k16.row.col.f32.f16.f16.f32 "
        "{%0,%1,%2,%3}, {%4,%5,%6,%7}, {%8,%9}, {%0,%1,%2,%3};"
        : "+f"(c[0]), "+f"(c[1]), "+f"(c[2]), "+f"(c[3])
        : "r"(a[0]), "r"(a[1]), "r"(a[2]), "r"(a[3]), "r"(b0), "r"(b1));
}

// ---------------------------------------------------------------------------
// util1: clear idx_map (all threads) + prep w2 fp16 Bh fragments (first 9216)
__global__ void util1_kernel(const float* __restrict__ w2) {
    int i = blockIdx.x * blockDim.x + threadIdx.x;
    if (i < HGRID * WGRID) g_idx_map[i] = -1;
    if (i < 9 * 4 * 8 * 32) {
        int lane = i & 31, nt = (i >> 5) & 7, kc = (i >> 8) & 3, tap = i >> 10;
        int n  = nt * 8 + (lane >> 2);
        int k0 = kc * 16 + (lane & 3) * 2;
        uint32_t p0 = pack_h2(w2[tap * 4096 + k0 * 64 + n],
                              w2[tap * 4096 + (k0 + 1) * 64 + n]);
        uint32_t p1 = pack_h2(w2[tap * 4096 + (k0 + 8) * 64 + n],
                              w2[tap * 4096 + (k0 + 9) * 64 + n]);
        g_w2h[i] = make_uint2(p0, p1);
    }
}

// util2: scatter coords + prep w3 bf16 frags (i<4096) + w1 bf16 frags ([4096,8192))
__global__ void util2_kernel(const int* __restrict__ coords,
                             const float* __restrict__ w3,
                             const float* __restrict__ w1, int n) {
    int i = blockIdx.x * blockDim.x + threadIdx.x;
    if (i < n) {
        int is64 = coords_is64(coords);
        g_idx_map[load_coord(coords, is64, i)] = i;
    }
    if (i < 4 * 4 * 8 * 32) {
        int lane = i & 31, nt = (i >> 5) & 7, kc = (i >> 8) & 3, cb = i >> 10;
        int nn = cb * 64 + nt * 8 + (lane >> 2);
        int k0 = kc * 16 + (lane & 3) * 2;
        uint32_t hi[2], lo[2];
#pragma unroll
        for (int j = 0; j < 2; ++j) {
            int k = k0 + j * 8;
            bsplit2(w3[k * 256 + nn], w3[(k + 1) * 256 + nn], hi[j], lo[j]);
        }
        g_w3f[i] = make_uint4(hi[0], hi[1], lo[0], lo[1]);
    } else if (i < 8192) {
        int j = i - 4096;
        int lane = j & 31, nt = (j >> 5) & 7, kc = j >> 8;   // kc 0..15
        int nn = nt * 8 + (lane >> 2);
        int k0 = kc * 16 + (lane & 3) * 2;
        uint32_t hi[2], lo[2];
#pragma unroll
        for (int q = 0; q < 2; ++q) {
            int k = k0 + q * 8;
            bsplit2(w1[k * 64 + nn], w1[(k + 1) * 64 + nn], hi[q], lo[q]);
        }
        g_w1f[j] = make_uint4(hi[0], hi[1], lo[0], lo[1]);
    }
}

// ---------------------------------------------------------------------------
// conv1 via bf16 3-term mma (R13); OUTPUT now packed as fp16 hi/lo planes.
#define LDF 144
#define FPL (128 * LDF)
#define S1_SC 0
#define S1_F  512
#define S1_B  37376
#define S1_TOTAL 53760

__global__ void __launch_bounds__(256, 3) conv1_mma_kernel(
    const float* __restrict__ feats,
    const float* __restrict__ s1, const float* __restrict__ b1, int n)
{
    extern __shared__ __align__(128) char dsm1[];
    float* s_s1 = (float*)(dsm1 + S1_SC);
    float* s_b1 = s_s1 + 64;
    unsigned char* sF = (unsigned char*)(dsm1 + S1_F);
    uint4* Bsm = (uint4*)(dsm1 + S1_B);

    const int tid = threadIdx.x, wid = tid >> 5, lane = tid & 31;
    const int site0 = blockIdx.x * 128;
    const int rw = wid * 16;
    const int frow = tid >> 3, fc8 = tid & 7;

    if (tid < 64) { s_s1[tid] = s1[tid]; s_b1[tid] = b1[tid]; }

    const uint32_t f_sm = smem_u32(sF);
    const uint32_t b_sm = smem_u32(Bsm);

    auto issue_ck = [&](int ck) {
        uint32_t fdst = f_sm + (ck & 1) * FPL;
#pragma unroll
        for (int g = 0; g < 4; ++g) {
            int row = frow + g * 32;
            int site = site0 + row;
            const char* src = (const char*)feats +
                (size_t)(site < n ? site : 0) * 1024 + ck * 128 + fc8 * 16;
            cp_async16_cg(fdst + row * LDF + fc8 * 16, src, site < n ? 16 : 0);
        }
        const uint4* bs = g_w1f + (size_t)ck * 512 + tid * 2;
        uint32_t bd = b_sm + (ck & 1) * 8192 + tid * 32;
        cp_async16_cg(bd, bs, 16);
        cp_async16_cg(bd + 16, bs + 1, 16);
        CP_COMMIT();
    };

    float acc[8][4];
#pragma unroll
    for (int t = 0; t < 8; ++t)
#pragma unroll
        for (int j = 0; j < 4; ++j) acc[t][j] = 0.f;

    issue_ck(0);

#pragma unroll 1
    for (int ck = 0; ck < 8; ++ck) {
        CP_WAIT0();
        __syncthreads();
        if (ck < 7) issue_ck(ck + 1);

        const unsigned char* fb = sF + (ck & 1) * FPL;
        const uint4* Bcur = Bsm + (ck & 1) * 512;
#pragma unroll
        for (int kh = 0; kh < 2; ++kh) {
            uint32_t ab = (uint32_t)((rw + (lane >> 2)) * LDF + kh * 64 + (lane & 3) * 8);
            float2 p00 = *(const float2*)(fb + ab);
            float2 p10 = *(const float2*)(fb + ab + 8 * LDF);
            float2 p01 = *(const float2*)(fb + ab + 32);
            float2 p11 = *(const float2*)(fb + ab + 8 * LDF + 32);
            uint32_t ah[4], al[4];
            bsplit2(p00.x, p00.y, ah[0], al[0]);
            bsplit2(p10.x, p10.y, ah[1], al[1]);
            bsplit2(p01.x, p01.y, ah[2], al[2]);
            bsplit2(p11.x, p11.y, ah[3], al[3]);
#pragma unroll
            for (int nt = 0; nt < 8; ++nt) {
                uint4 b = Bcur[kh * 256 + nt * 32 + lane];
                mma16816(acc[nt], ah, b.x, b.y);
                mma16816(acc[nt], ah, b.z, b.w);
                mma16816(acc[nt], al, b.x, b.y);
            }
        }
    }
    __syncthreads();

    // epilogue: bn1 + relu, FP16 split, stage rows {128B hi,128B lo}, write
    uint32_t* sh = (uint32_t*)sF;
    {
        int r0 = rw + (lane >> 2);
        int n0 = (lane & 3) * 2;
#pragma unroll
        for (int nt = 0; nt < 8; ++nt) {
            int c0 = nt * 8 + n0;
            int wc = nt * 4 + (lane & 3);
            float v0 = fmaxf(fmaf(acc[nt][0], s_s1[c0],     s_b1[c0]),     0.f);
            float v1 = fmaxf(fmaf(acc[nt][1], s_s1[c0 + 1], s_b1[c0 + 1]), 0.f);
            float v2 = fmaxf(fmaf(acc[nt][2], s_s1[c0],     s_b1[c0]),     0.f);
            float v3 = fmaxf(fmaf(acc[nt][3], s_s1[c0 + 1], s_b1[c0 + 1]), 0.f);
            uint32_t h, l;
            hsplit2(v0, v1, h, l);
            sh[r0 * 64 + wc] = h; sh[r0 * 64 + 32 + wc] = l;
            hsplit2(v2, v3, h, l);
            sh[(r0 + 8) * 64 + wc] = h; sh[(r0 + 8) * 64 + 32 + wc] = l;
        }
    }
    __syncthreads();
    {
        int chunk = tid & 15, rbase = tid >> 4;
#pragma unroll
        for (int it = 0; it < 8; ++it) {
            int row = rbase + it * 16;
            uint4 v = *(const uint4*)((const char*)sh + row * 256 + chunk * 16);
            *(uint4*)(g_h1b + (size_t)(site0 + row) * 256 + chunk * 16) = v;
        }
    }
}

// ---------------------------------------------------------------------------
// FUSED conv2 + conv3. conv2: fp16 2-term (A exact-split, B rounded), uint2
// B frags; conv3: bf16 3-term (unchanged). cp.async.cg double buffering.
#define APL 18432
#define ABF (2 * APL)
#define LDP 144
#define SM_SC    0
#define SM_NBR   2560
#define SM_A     7680                   // 2 * ABF -> ends 81408
#define SM_B     81408                  // 16KB: conv2 2x8KB taps / conv3 16KB
#define SM_TOTAL 97792

__global__ void __launch_bounds__(256) conv23_kernel(
    const int* __restrict__ coords,
    const float* __restrict__ s2, const float* __restrict__ b2,
    const float* __restrict__ feats,
    const float* __restrict__ s3, const float* __restrict__ b3,
    float* __restrict__ out, int n)
{
    extern __shared__ __align__(128) char dsm[];
    float* s_s2 = (float*)(dsm + SM_SC);
    float* s_b2 = s_s2 + 64;
    float* s_s3 = s_b2 + 64;
    float* s_b3 = s_s3 + 256;
    int*  s_nbr = (int*)(dsm + SM_NBR);
    unsigned char* Abuf = (unsigned char*)(dsm + SM_A);
    uint2* Bh2 = (uint2*)(dsm + SM_B);     // conv2 view: 2 x 1024 uint2
    uint4* Bsm4 = (uint4*)(dsm + SM_B);    // conv3 view: 1024 uint4

    const int tid = threadIdx.x, wid = tid >> 5, lane = tid & 31;
    const int site0 = blockIdx.x * 128;
    const int rw = wid * 16;

    const int sub  = lane >> 4;
    const int boff = (lane & 15) * 16;
    const int psel = boff >> 7;
    const int poff = boff & 127;

    if (tid < 64) { s_s2[tid] = s2[tid]; s_b2[tid] = b2[tid]; }
    s_s3[tid] = s3[tid]; s_b3[tid] = b3[tid];
    if (tid < 128) {
#pragma unroll
        for (int t = 0; t < 9; ++t) s_nbr[t * 128 + tid] = -1;
        int site = site0 + tid;
        if (site < n) {
            int is64 = coords_is64(coords);
            int c = load_coord(coords, is64, site);
            int y = c / WGRID, x = c % WGRID;
#pragma unroll
            for (int t = 0; t < 9; ++t) {
                int ny = y + t / 3 - 1, nx = x + t % 3 - 1;
                if (ny >= 0 && ny < HGRID && nx >= 0 && nx < WGRID)
                    s_nbr[t * 128 + tid] = g_idx_map[ny * WGRID + nx];
            }
        }
    }
    __syncthreads();

    float acc[8][4];
#pragma unroll
    for (int t = 0; t < 8; ++t)
#pragma unroll
        for (int j = 0; j < 4; ++j) acc[t][j] = 0.f;

    const uint32_t a_sm = smem_u32(Abuf);
    const uint32_t b_sm = smem_u32(Bh2);

    auto issue_tap = [&](int t) {
        uint32_t abase = a_sm + (t & 1) * ABF + psel * APL + poff;
#pragma unroll
        for (int g = 0; g < 8; ++g) {
            int row = rw + g * 2 + sub;
            int nb = s_nbr[t * 128 + row];
            const unsigned char* src = g_h1b + (size_t)(nb < 0 ? 0 : nb) * 256 + boff;
            cp_async16_cg(abase + row * LDP, src, nb >= 0 ? 16 : 0);
        }
        const uint2* bs = g_w2h + (size_t)t * 1024 + tid * 4;
        uint32_t bd = b_sm + (t & 1) * 8192 + tid * 32;
        cp_async16_cg(bd, bs, 16);
        cp_async16_cg(bd + 16, bs + 2, 16);
        CP_COMMIT();
    };

    issue_tap(0);

    // ---------------- conv2: 9-tap, fp16 2-term ----------------
#pragma unroll 1
    for (int tap = 0; tap < 9; ++tap) {
        CP_WAIT0();
        __syncthreads();
        if (tap < 8) issue_tap(tap + 1);

        const unsigned char* wbase = Abuf + (tap & 1) * ABF;
        const uint2* Bcur = Bh2 + (tap & 1) * 1024;
#pragma unroll
        for (int kc = 0; kc < 4; ++kc) {
            uint32_t ab = (uint32_t)((rw + (lane >> 2)) * LDP + kc * 32 + (lane & 3) * 4);
            uint32_t ah[4], al[4];
            ah[0] = *(const uint32_t*)(wbase + ab);
            ah[1] = *(const uint32_t*)(wbase + ab + 8 * LDP);
            ah[2] = *(const uint32_t*)(wbase + ab + 16);
            ah[3] = *(const uint32_t*)(wbase + ab + 8 * LDP + 16);
            al[0] = *(const uint32_t*)(wbase + APL + ab);
            al[1] = *(const uint32_t*)(wbase + APL + ab + 8 * LDP);
            al[2] = *(const uint32_t*)(wbase + APL + ab + 16);
            al[3] = *(const uint32_t*)(wbase + APL + ab + 8 * LDP + 16);
#pragma unroll
            for (int nt = 0; nt < 8; ++nt) {
                uint2 b = Bcur[kc * 256 + nt * 32 + lane];
                mma16816h(acc[nt], ah, b.x, b.y);   // Ah * Bh
                mma16816h(acc[nt], al, b.x, b.y);   // Al * Bh
            }
        }
    }
    __syncthreads();   // all warps finish MMA(tap 8) before buffer reuse

    // ------- bn2 + relu in registers; bf16 A-frags for conv3 --------
    uint32_t fh[4][4], fl[4][4];
    {
        const int n0 = (lane & 3) * 2;
#pragma unroll
        for (int kc = 0; kc < 4; ++kc) {
#pragma unroll
            for (int q = 0; q < 2; ++q) {
                int nt = 2 * kc + q;
                int c0 = nt * 8 + n0;
                float v0 = fmaxf(fmaf(acc[nt][0], s_s2[c0],     s_b2[c0]),     0.f);
                float v1 = fmaxf(fmaf(acc[nt][1], s_s2[c0 + 1], s_b2[c0 + 1]), 0.f);
                float v2 = fmaxf(fmaf(acc[nt][2], s_s2[c0],     s_b2[c0]),     0.f);
                float v3 = fmaxf(fmaf(acc[nt][3], s_s2[c0 + 1], s_b2[c0 + 1]), 0.f);
                bsplit2(v0, v1, fh[kc][2 * q],     fl[kc][2 * q]);
                bsplit2(v2, v3, fh[kc][2 * q + 1], fl[kc][2 * q + 1]);
            }
        }
    }

    // ---------------- conv3: bf16 3-term (unchanged) --------------
    float* stg = (float*)Abuf;
    {
        const uint4* bs = g_w3f + tid * 4;
#pragma unroll
        for (int q = 0; q < 4; ++q) Bsm4[tid * 4 + q] = bs[q];
    }
    __syncthreads();

#pragma unroll 1
    for (int cb = 0; cb < 4; ++cb) {
        float acc2[8][4];
#pragma unroll
        for (int t = 0; t < 8; ++t)
#pragma unroll
            for (int j = 0; j < 4; ++j) acc2[t][j] = 0.f;

#pragma unroll
        for (int kc = 0; kc < 4; ++kc) {
#pragma unroll
            for (int nt = 0; nt < 8; ++nt) {
                uint4 b = Bsm4[kc * 256 + nt * 32 + lane];
                mma16816(acc2[nt], fh[kc], b.x, b.y);
                mma16816(acc2[nt], fh[kc], b.z, b.w);
                mma16816(acc2[nt], fl[kc], b.x, b.y);
            }
        }
        __syncthreads();
        {
            int r0 = rw + (lane >> 2);
            int n0 = (lane & 3) * 2;
#pragma unroll
            for (int nt = 0; nt < 8; ++nt) {
                int c  = nt * 8 + n0;
                int cg = cb * 64 + c;
                stg[r0 * 64 + c]           = fmaf(acc2[nt][0], s_s3[cg],     s_b3[cg]);
                stg[r0 * 64 + c + 1]       = fmaf(acc2[nt][1], s_s3[cg + 1], s_b3[cg + 1]);
                stg[(r0 + 8) * 64 + c]     = fmaf(acc2[nt][2], s_s3[cg],     s_b3[cg]);
                stg[(r0 + 8) * 64 + c + 1] = fmaf(acc2[nt][3], s_s3[cg + 1], s_b3[cg + 1]);
            }
        }
        if (cb < 3) {
            const uint4* bs = g_w3f + (size_t)(cb + 1) * 1024 + tid * 4;
#pragma unroll
            for (int q = 0; q < 4; ++q) Bsm4[tid * 4 + q] = bs[q];
        }
        __syncthreads();
        {
#pragma unroll
            for (int g = 0; g < 8; ++g) {
                int row = rw + g * 2 + sub;
                int site = site0 + row;
                if (site < n) {
                    float4 a = *(const float4*)((const char*)stg + row * 256 + boff);
                    float4 b = *(const float4*)((const char*)feats +
                                                (size_t)site * 1024 + cb * 256 + boff);
                    float4 o;
                    o.x = fmaxf(a.x + b.x, 0.f);
                    o.y = fmaxf(a.y + b.y, 0.f);
                    o.z = fmaxf(a.z + b.z, 0.f);
                    o.w = fmaxf(a.w + b.w, 0.f);
                    *(float4*)((char*)out + (size_t)site * 1024 + cb * 256 + boff) = o;
                }
            }
        }
    }
}

// ---------------------------------------------------------------------------
extern "C" void kernel_launch(void* const* d_in, const int* in_sizes, int n_in,
                              void* d_out, int out_size) {
    const float* feats  = (const float*)d_in[0];
    const int*   coords = (const int*)d_in[1];
    const float* w1     = (const float*)d_in[2];
    const float* w2     = (const float*)d_in[3];
    const float* w3     = (const float*)d_in[4];
    const float* s1     = (const float*)d_in[5];
    const float* b1     = (const float*)d_in[6];
    const float* s2     = (const float*)d_in[7];
    const float* b2     = (const float*)d_in[8];
    const float* s3     = (const float*)d_in[9];
    const float* b3     = (const float*)d_in[10];
    float* out = (float*)d_out;

    const int n = in_sizes[0] / 256;
    const int tiles = (n + 127) / 128;

    cudaFuncSetAttribute(conv1_mma_kernel,
                         cudaFuncAttributeMaxDynamicSharedMemorySize, S1_TOTAL);
    cudaFuncSetAttribute(conv23_kernel,
                         cudaFuncAttributeMaxDynamicSharedMemorySize, SM_TOTAL);

    // 4 launches; conv23 is launch #4 so ncu (-s/-c window) captures it.
    util1_kernel<<<(HGRID * WGRID + 255) / 256, 256>>>(w2);                   // #1
    util2_kernel<<<(max(n, 8192) + 255) / 256, 256>>>(coords, w3, w1, n);     // #2
    conv1_mma_kernel<<<tiles, 256, S1_TOTAL>>>(feats, s1, b1, n);             // #3
    conv23_kernel<<<tiles, 256, SM_TOTAL>>>(coords, s2, b2, feats, s3, b3, out, n);  // #4
}

// round 15
// speedup vs baseline: 3.1503x; 1.4073x over previous
#include <cuda_runtime.h>
#include <cuda_bf16.h>
#include <cuda_fp16.h>
#include <cstdint>

#define HGRID 768
#define WGRID 768
#define NMAX  200064   // 1563 * 128

// Scratch in __device__ globals (no allocation allowed).
__device__ int g_idx_map[HGRID * WGRID];
// h1 as plain fp16 rows: 128B per site (64 x fp16)
__device__ __align__(16) unsigned char g_h1b[(size_t)NMAX * 128];
// Weight fragments:
__device__ uint4 g_w1f[16 * 8 * 32];      // w1 bf16 3-term: [kc(16)][nt(8)][lane]
__device__ uint2 g_w2h[9 * 4 * 8 * 32];   // w2 fp16: [tap][kc][nt][lane]
__device__ uint2 g_w3h[4 * 4 * 8 * 32];   // w3 fp16: [cb][kc][nt][lane]

// ---------------------------------------------------------------------------
__device__ __forceinline__ int coords_is64(const int* c) { return c[1] == 0; }
__device__ __forceinline__ int load_coord(const int* c, int is64, int i) {
    return is64 ? c[2 * i] : c[i];
}
__device__ __forceinline__ void bsplit2(float a, float b, uint32_t& hi, uint32_t& lo) {
    __nv_bfloat16 ah = __float2bfloat16(a);
    __nv_bfloat16 bh = __float2bfloat16(b);
    float ar = a - __bfloat162float(ah);
    float br = b - __bfloat162float(bh);
    __nv_bfloat162 h; h.x = ah; h.y = bh;
    __nv_bfloat162 l; l.x = __float2bfloat16(ar); l.y = __float2bfloat16(br);
    hi = *reinterpret_cast<uint32_t*>(&h);
    lo = *reinterpret_cast<uint32_t*>(&l);
}
// fp16 exact split: a = hi + lo to ~2^-22
__device__ __forceinline__ void hsplit2(float a, float b, uint32_t& hi, uint32_t& lo) {
    __half ah = __float2half_rn(a);
    __half bh = __float2half_rn(b);
    float ar = a - __half2float(ah);
    float br = b - __half2float(bh);
    __half2 h; h.x = ah; h.y = bh;
    __half2 l; l.x = __float2half_rn(ar); l.y = __float2half_rn(br);
    hi = *reinterpret_cast<uint32_t*>(&h);
    lo = *reinterpret_cast<uint32_t*>(&l);
}
__device__ __forceinline__ uint32_t pack_h2(float a, float b) {
    __half2 h; h.x = __float2half_rn(a); h.y = __float2half_rn(b);
    return *reinterpret_cast<uint32_t*>(&h);
}
__device__ __forceinline__ uint32_t smem_u32(const void* p) {
    uint32_t a;
    asm("{ .reg .u64 t; cvta.to.shared.u64 t, %1; cvt.u32.u64 %0, t; }"
        : "=r"(a) : "l"(p));
    return a;
}
// L2-direct async copy (bypasses L1)
__device__ __forceinline__ void cp_async16_cg(uint32_t dst, const void* src, int srcsize) {
    asm volatile("cp.async.cg.shared.global [%0], [%1], 16, %2;"
                 :: "r"(dst), "l"(src), "r"(srcsize) : "memory");
}
#define CP_COMMIT() asm volatile("cp.async.commit_group;" ::: "memory")
#define CP_WAIT0()  asm volatile("cp.async.wait_group 0;" ::: "memory")

// mma.sync m16n8k16 bf16 -> f32 accumulate
__device__ __forceinline__ void mma16816(float c[4], const uint32_t a[4],
                                         uint32_t b0, uint32_t b1) {
    asm volatile(
        "mma.sync.aligned.m16n8k16.row.col.f32.bf16.bf16.f32 "
        "{%0,%1,%2,%3}, {%4,%5,%6,%7}, {%8,%9}, {%0,%1,%2,%3};"
        : "+f"(c[0]), "+f"(c[1]), "+f"(c[2]), "+f"(c[3])
        : "r"(a[0]), "r"(a[1]), "r"(a[2]), "r"(a[3]), "r"(b0), "r"(b1));
}
// mma.sync m16n8k16 fp16 -> f32 accumulate
__device__ __forceinline__ void mma16816h(float c[4], const uint32_t a[4],
                                          uint32_t b0, uint32_t b1) {
    asm volatile(
        "mma.sync.aligned.m16n8k16.row.col.f32.f16.f16.f32 "
        "{%0,%1,%2,%3}, {%4,%5,%6,%7}, {%8,%9}, {%0,%1,%2,%3};"
        : "+f"(c[0]), "+f"(c[1]), "+f"(c[2]), "+f"(c[3])
        : "r"(a[0]), "r"(a[1]), "r"(a[2]), "r"(a[3]), "r"(b0), "r"(b1));
}

// ---------------------------------------------------------------------------
// util1: clear idx_map (all threads) + prep w2 fp16 fragments (first 9216)
__global__ void util1_kernel(const float* __restrict__ w2) {
    int i = blockIdx.x * blockDim.x + threadIdx.x;
    if (i < HGRID * WGRID) g_idx_map[i] = -1;
    if (i < 9 * 4 * 8 * 32) {
        int lane = i & 31, nt = (i >> 5) & 7, kc = (i >> 8) & 3, tap = i >> 10;
        int n  = nt * 8 + (lane >> 2);
        int k0 = kc * 16 + (lane & 3) * 2;
        uint32_t p0 = pack_h2(w2[tap * 4096 + k0 * 64 + n],
                              w2[tap * 4096 + (k0 + 1) * 64 + n]);
        uint32_t p1 = pack_h2(w2[tap * 4096 + (k0 + 8) * 64 + n],
                              w2[tap * 4096 + (k0 + 9) * 64 + n]);
        g_w2h[i] = make_uint2(p0, p1);
    }
}

// util2: scatter coords + prep w3 fp16 frags (i<4096) + w1 bf16 frags ([4096,8192))
__global__ void util2_kernel(const int* __restrict__ coords,
                             const float* __restrict__ w3,
                             const float* __restrict__ w1, int n) {
    int i = blockIdx.x * blockDim.x + threadIdx.x;
    if (i < n) {
        int is64 = coords_is64(coords);
        g_idx_map[load_coord(coords, is64, i)] = i;
    }
    if (i < 4 * 4 * 8 * 32) {
        int lane = i & 31, nt = (i >> 5) & 7, kc = (i >> 8) & 3, cb = i >> 10;
        int nn = cb * 64 + nt * 8 + (lane >> 2);
        int k0 = kc * 16 + (lane & 3) * 2;
        uint32_t p0 = pack_h2(w3[k0 * 256 + nn], w3[(k0 + 1) * 256 + nn]);
        uint32_t p1 = pack_h2(w3[(k0 + 8) * 256 + nn], w3[(k0 + 9) * 256 + nn]);
        g_w3h[i] = make_uint2(p0, p1);
    } else if (i < 8192) {
        int j = i - 4096;
        int lane = j & 31, nt = (j >> 5) & 7, kc = j >> 8;   // kc 0..15
        int nn = nt * 8 + (lane >> 2);
        int k0 = kc * 16 + (lane & 3) * 2;
        uint32_t hi[2], lo[2];
#pragma unroll
        for (int q = 0; q < 2; ++q) {
            int k = k0 + q * 8;
            bsplit2(w1[k * 64 + nn], w1[(k + 1) * 64 + nn], hi[q], lo[q]);
        }
        g_w1f[j] = make_uint4(hi[0], hi[1], lo[0], lo[1]);
    }
}

// ---------------------------------------------------------------------------
// conv1 via bf16 3-term mma; OUTPUT: plain fp16 rows (128B/site).
#define LDF 144
#define FPL (128 * LDF)
#define S1_SC 0
#define S1_F  512
#define S1_B  37376
#define S1_TOTAL 53760

__global__ void __launch_bounds__(256, 3) conv1_mma_kernel(
    const float* __restrict__ feats,
    const float* __restrict__ s1, const float* __restrict__ b1, int n)
{
    extern __shared__ __align__(128) char dsm1[];
    float* s_s1 = (float*)(dsm1 + S1_SC);
    float* s_b1 = s_s1 + 64;
    unsigned char* sF = (unsigned char*)(dsm1 + S1_F);
    uint4* Bsm = (uint4*)(dsm1 + S1_B);

    const int tid = threadIdx.x, wid = tid >> 5, lane = tid & 31;
    const int site0 = blockIdx.x * 128;
    const int rw = wid * 16;
    const int frow = tid >> 3, fc8 = tid & 7;

    if (tid < 64) { s_s1[tid] = s1[tid]; s_b1[tid] = b1[tid]; }

    const uint32_t f_sm = smem_u32(sF);
    const uint32_t b_sm = smem_u32(Bsm);

    auto issue_ck = [&](int ck) {
        uint32_t fdst = f_sm + (ck & 1) * FPL;
#pragma unroll
        for (int g = 0; g < 4; ++g) {
            int row = frow + g * 32;
            int site = site0 + row;
            const char* src = (const char*)feats +
                (size_t)(site < n ? site : 0) * 1024 + ck * 128 + fc8 * 16;
            cp_async16_cg(fdst + row * LDF + fc8 * 16, src, site < n ? 16 : 0);
        }
        const uint4* bs = g_w1f + (size_t)ck * 512 + tid * 2;
        uint32_t bd = b_sm + (ck & 1) * 8192 + tid * 32;
        cp_async16_cg(bd, bs, 16);
        cp_async16_cg(bd + 16, bs + 1, 16);
        CP_COMMIT();
    };

    float acc[8][4];
#pragma unroll
    for (int t = 0; t < 8; ++t)
#pragma unroll
        for (int j = 0; j < 4; ++j) acc[t][j] = 0.f;

    issue_ck(0);

#pragma unroll 1
    for (int ck = 0; ck < 8; ++ck) {
        CP_WAIT0();
        __syncthreads();
        if (ck < 7) issue_ck(ck + 1);

        const unsigned char* fb = sF + (ck & 1) * FPL;
        const uint4* Bcur = Bsm + (ck & 1) * 512;
#pragma unroll
        for (int kh = 0; kh < 2; ++kh) {
            uint32_t ab = (uint32_t)((rw + (lane >> 2)) * LDF + kh * 64 + (lane & 3) * 8);
            float2 p00 = *(const float2*)(fb + ab);
            float2 p10 = *(const float2*)(fb + ab + 8 * LDF);
            float2 p01 = *(const float2*)(fb + ab + 32);
            float2 p11 = *(const float2*)(fb + ab + 8 * LDF + 32);
            uint32_t ah[4], al[4];
            bsplit2(p00.x, p00.y, ah[0], al[0]);
            bsplit2(p10.x, p10.y, ah[1], al[1]);
            bsplit2(p01.x, p01.y, ah[2], al[2]);
            bsplit2(p11.x, p11.y, ah[3], al[3]);
#pragma unroll
            for (int nt = 0; nt < 8; ++nt) {
                uint4 b = Bcur[kh * 256 + nt * 32 + lane];
                mma16816(acc[nt], ah, b.x, b.y);
                mma16816(acc[nt], ah, b.z, b.w);
                mma16816(acc[nt], al, b.x, b.y);
            }
        }
    }
    __syncthreads();

    // epilogue: bn1 + relu, round to fp16, stage 128B rows, coalesced write
    uint32_t* sh = (uint32_t*)sF;   // 128 rows x 32 words (128B)
    {
        int r0 = rw + (lane >> 2);
        int n0 = (lane & 3) * 2;
#pragma unroll
        for (int nt = 0; nt < 8; ++nt) {
            int c0 = nt * 8 + n0;
            int wc = nt * 4 + (lane & 3);
            float v0 = fmaxf(fmaf(acc[nt][0], s_s1[c0],     s_b1[c0]),     0.f);
            float v1 = fmaxf(fmaf(acc[nt][1], s_s1[c0 + 1], s_b1[c0 + 1]), 0.f);
            float v2 = fmaxf(fmaf(acc[nt][2], s_s1[c0],     s_b1[c0]),     0.f);
            float v3 = fmaxf(fmaf(acc[nt][3], s_s1[c0 + 1], s_b1[c0 + 1]), 0.f);
            sh[r0 * 32 + wc]       = pack_h2(v0, v1);
            sh[(r0 + 8) * 32 + wc] = pack_h2(v2, v3);
        }
    }
    __syncthreads();
    {   // 8 lanes per 128B row, 32 rows per pass, 4 passes
        int chunk = tid & 7, rbase = tid >> 3;
#pragma unroll
        for (int it = 0; it < 4; ++it) {
            int row = rbase + it * 32;
            uint4 v = *(const uint4*)((const char*)sh + row * 128 + chunk * 16);
            *(uint4*)(g_h1b + (size_t)(site0 + row) * 128 + chunk * 16) = v;
        }
    }
}

// ---------------------------------------------------------------------------
// FUSED conv2 + conv3. conv2: pure fp16 (1 MMA/step, single A plane);
// conv3: fp16 2-term (exact h2 split + rounded w3). cp.async.cg dbl-buffer.
#define APL 18432                       // A plane buffer: 128 rows * 144B
#define LDP 144
#define SM_SC    0                      // 2560
#define SM_NBR   2560                   // 4608 -> ends 7168
#define SM_A     7680                   // 2 * APL = 36864 -> ends 44544
#define SM_B     44544                  // 16384 (conv2 2x8KB / conv3 8KB) -> 60928
#define SM_TOTAL 60928

__global__ void __launch_bounds__(256) conv23_kernel(
    const int* __restrict__ coords,
    const float* __restrict__ s2, const float* __restrict__ b2,
    const float* __restrict__ feats,
    const float* __restrict__ s3, const float* __restrict__ b3,
    float* __restrict__ out, int n)
{
    extern __shared__ __align__(128) char dsm[];
    float* s_s2 = (float*)(dsm + SM_SC);
    float* s_b2 = s_s2 + 64;
    float* s_s3 = s_b2 + 64;
    float* s_b3 = s_s3 + 256;
    int*  s_nbr = (int*)(dsm + SM_NBR);
    unsigned char* Abuf = (unsigned char*)(dsm + SM_A);
    uint2* Bh2 = (uint2*)(dsm + SM_B);

    const int tid = threadIdx.x, wid = tid >> 5, lane = tid & 31;
    const int site0 = blockIdx.x * 128;
    const int rw = wid * 16;

    // gather mapping: 8 lanes per 128B h1 row; 4 rows per iter
    const int sub4  = lane >> 3;          // 0..3: row within group of 4
    const int boff8 = (lane & 7) * 16;    // byte chunk within 128B row
    // epilogue mapping: 16 lanes per 256B f32 row
    const int sub  = lane >> 4;
    const int boff = (lane & 15) * 16;

    if (tid < 64) { s_s2[tid] = s2[tid]; s_b2[tid] = b2[tid]; }
    s_s3[tid] = s3[tid]; s_b3[tid] = b3[tid];
    if (tid < 128) {
#pragma unroll
        for (int t = 0; t < 9; ++t) s_nbr[t * 128 + tid] = -1;
        int site = site0 + tid;
        if (site < n) {
            int is64 = coords_is64(coords);
            int c = load_coord(coords, is64, site);
            int y = c / WGRID, x = c % WGRID;
#pragma unroll
            for (int t = 0; t < 9; ++t) {
                int ny = y + t / 3 - 1, nx = x + t % 3 - 1;
                if (ny >= 0 && ny < HGRID && nx >= 0 && nx < WGRID)
                    s_nbr[t * 128 + tid] = g_idx_map[ny * WGRID + nx];
            }
        }
    }
    __syncthreads();

    float acc[8][4];
#pragma unroll
    for (int t = 0; t < 8; ++t)
#pragma unroll
        for (int j = 0; j < 4; ++j) acc[t][j] = 0.f;

    const uint32_t a_sm = smem_u32(Abuf);
    const uint32_t b_sm = smem_u32(Bh2);

    auto issue_tap = [&](int t) {
        uint32_t abase = a_sm + (t & 1) * APL + boff8;
#pragma unroll
        for (int g = 0; g < 4; ++g) {
            int row = rw + g * 4 + sub4;
            int nb = s_nbr[t * 128 + row];
            const unsigned char* src = g_h1b + (size_t)(nb < 0 ? 0 : nb) * 128 + boff8;
            cp_async16_cg(abase + row * LDP, src, nb >= 0 ? 16 : 0);
        }
        const uint2* bs = g_w2h + (size_t)t * 1024 + tid * 4;
        uint32_t bd = b_sm + (t & 1) * 8192 + tid * 32;
        cp_async16_cg(bd, bs, 16);
        cp_async16_cg(bd + 16, bs + 2, 16);
        CP_COMMIT();
    };

    issue_tap(0);

    // ---------------- conv2: 9-tap, pure fp16, 1 MMA per step -------------
#pragma unroll 1
    for (int tap = 0; tap < 9; ++tap) {
        CP_WAIT0();
        __syncthreads();
        if (tap < 8) issue_tap(tap + 1);

        const unsigned char* wbase = Abuf + (tap & 1) * APL;
        const uint2* Bcur = Bh2 + (tap & 1) * 1024;
#pragma unroll
        for (int kc = 0; kc < 4; ++kc) {
            uint32_t ab = (uint32_t)((rw + (lane >> 2)) * LDP + kc * 32 + (lane & 3) * 4);
            uint32_t ah[4];
            ah[0] = *(const uint32_t*)(wbase + ab);
            ah[1] = *(const uint32_t*)(wbase + ab + 8 * LDP);
            ah[2] = *(const uint32_t*)(wbase + ab + 16);
            ah[3] = *(const uint32_t*)(wbase + ab + 8 * LDP + 16);
#pragma unroll
            for (int nt = 0; nt < 8; ++nt) {
                uint2 b = Bcur[kc * 256 + nt * 32 + lane];
                mma16816h(acc[nt], ah, b.x, b.y);
            }
        }
    }
    __syncthreads();   // all warps finish MMA(tap 8) before buffer reuse

    // --- bn2 + relu in registers; EXACT fp16 split -> conv3 A-frags -------
    uint32_t fh[4][4], fl[4][4];
    {
        const int n0 = (lane & 3) * 2;
#pragma unroll
        for (int kc = 0; kc < 4; ++kc) {
#pragma unroll
            for (int q = 0; q < 2; ++q) {
                int nt = 2 * kc + q;
                int c0 = nt * 8 + n0;
                float v0 = fmaxf(fmaf(acc[nt][0], s_s2[c0],     s_b2[c0]),     0.f);
                float v1 = fmaxf(fmaf(acc[nt][1], s_s2[c0 + 1], s_b2[c0 + 1]), 0.f);
                float v2 = fmaxf(fmaf(acc[nt][2], s_s2[c0],     s_b2[c0]),     0.f);
                float v3 = fmaxf(fmaf(acc[nt][3], s_s2[c0 + 1], s_b2[c0 + 1]), 0.f);
                hsplit2(v0, v1, fh[kc][2 * q],     fl[kc][2 * q]);
                hsplit2(v2, v3, fh[kc][2 * q + 1], fl[kc][2 * q + 1]);
            }
        }
    }

    // ---------------- conv3: fp16 2-term, 4 column blocks -----------------
    float* stg = (float*)Abuf;   // 128 x 64 f32 staging = 32KB (fits 2*APL)
    {   // preload cb=0 B fragments
        const uint2* bs = g_w3h + tid * 4;
#pragma unroll
        for (int q = 0; q < 4; ++q) Bh2[tid * 4 + q] = bs[q];
    }
    __syncthreads();

#pragma unroll 1
    for (int cb = 0; cb < 4; ++cb) {
        float acc2[8][4];
#pragma unroll
        for (int t = 0; t < 8; ++t)
#pragma unroll
            for (int j = 0; j < 4; ++j) acc2[t][j] = 0.f;

#pragma unroll
        for (int kc = 0; kc < 4; ++kc) {
#pragma unroll
            for (int nt = 0; nt < 8; ++nt) {
                uint2 b = Bh2[kc * 256 + nt * 32 + lane];
                mma16816h(acc2[nt], fh[kc], b.x, b.y);
                mma16816h(acc2[nt], fl[kc], b.x, b.y);
            }
        }
        __syncthreads();   // B reads done; stg free (prev write-out done)
        {
            int r0 = rw + (lane >> 2);
            int n0 = (lane & 3) * 2;
#pragma unroll
            for (int nt = 0; nt < 8; ++nt) {
                int c  = nt * 8 + n0;
                int cg = cb * 64 + c;
                stg[r0 * 64 + c]           = fmaf(acc2[nt][0], s_s3[cg],     s_b3[cg]);
                stg[r0 * 64 + c + 1]       = fmaf(acc2[nt][1], s_s3[cg + 1], s_b3[cg + 1]);
                stg[(r0 + 8) * 64 + c]     = fmaf(acc2[nt][2], s_s3[cg],     s_b3[cg]);
                stg[(r0 + 8) * 64 + c + 1] = fmaf(acc2[nt][3], s_s3[cg + 1], s_b3[cg + 1]);
            }
        }
        if (cb < 3) {   // stage next cb's B fragments
            const uint2* bs = g_w3h + (size_t)(cb + 1) * 1024 + tid * 4;
#pragma unroll
            for (int q = 0; q < 4; ++q) Bh2[tid * 4 + q] = bs[q];
        }
        __syncthreads();   // stg + next B visible
        {   // coalesced residual+relu+write: 16 lanes per 256B row
#pragma unroll
            for (int g = 0; g < 8; ++g) {
                int row = rw + g * 2 + sub;
                int site = site0 + row;
                if (site < n) {
                    float4 a = *(const float4*)((const char*)stg + row * 256 + boff);
                    float4 b = *(const float4*)((const char*)feats +
                                                (size_t)site * 1024 + cb * 256 + boff);
                    float4 o;
                    o.x = fmaxf(a.x + b.x, 0.f);
                    o.y = fmaxf(a.y + b.y, 0.f);
                    o.z = fmaxf(a.z + b.z, 0.f);
                    o.w = fmaxf(a.w + b.w, 0.f);
                    *(float4*)((char*)out + (size_t)site * 1024 + cb * 256 + boff) = o;
                }
            }
        }
    }
}

// ---------------------------------------------------------------------------
extern "C" void kernel_launch(void* const* d_in, const int* in_sizes, int n_in,
                              void* d_out, int out_size) {
    const float* feats  = (const float*)d_in[0];
    const int*   coords = (const int*)d_in[1];
    const float* w1     = (const float*)d_in[2];
    const float* w2     = (const float*)d_in[3];
    const float* w3     = (const float*)d_in[4];
    const float* s1     = (const float*)d_in[5];
    const float* b1     = (const float*)d_in[6];
    const float* s2     = (const float*)d_in[7];
    const float* b2     = (const float*)d_in[8];
    const float* s3     = (const float*)d_in[9];
    const float* b3     = (const float*)d_in[10];
    float* out = (float*)d_out;

    const int n = in_sizes[0] / 256;
    const int tiles = (n + 127) / 128;

    cudaFuncSetAttribute(conv1_mma_kernel,
                         cudaFuncAttributeMaxDynamicSharedMemorySize, S1_TOTAL);
    cudaFuncSetAttribute(conv23_kernel,
                         cudaFuncAttributeMaxDynamicSharedMemorySize, SM_TOTAL);

    // 4 launches; conv23 is launch #4 so ncu (-s/-c window) captures it.
    util1_kernel<<<(HGRID * WGRID + 255) / 256, 256>>>(w2);                   // #1
    util2_kernel<<<(max(n, 8192) + 255) / 256, 256>>>(coords, w3, w1, n);     // #2
    conv1_mma_kernel<<<tiles, 256, S1_TOTAL>>>(feats, s1, b1, n);             // #3
    conv23_kernel<<<tiles, 256, SM_TOTAL>>>(coords, s2, b2, feats, s3, b3, out, n);  // #4
}

// round 16
// speedup vs baseline: 3.4797x; 1.1046x over previous
#include <cuda_runtime.h>
#include <cuda_bf16.h>
#include <cuda_fp16.h>
#include <cstdint>

#define HGRID 768
#define WGRID 768
#define NMAX  200064   // 1563 * 128

// Scratch in __device__ globals (no allocation allowed).
__device__ int g_idx_map[HGRID * WGRID];
// h1 as plain fp16 rows: 128B per site (64 x fp16)
__device__ __align__(16) unsigned char g_h1b[(size_t)NMAX * 128];
// Weight fragments (fp16):
__device__ uint2 g_w1h[16 * 8 * 32];      // w1: [kc(16)][nt(8)][lane]
__device__ uint2 g_w2h[9 * 4 * 8 * 32];   // w2: [tap][kc][nt][lane]
__device__ uint2 g_w3h[4 * 4 * 8 * 32];   // w3: [cb][kc][nt][lane]

// ---------------------------------------------------------------------------
__device__ __forceinline__ int coords_is64(const int* c) { return c[1] == 0; }
__device__ __forceinline__ int load_coord(const int* c, int is64, int i) {
    return is64 ? c[2 * i] : c[i];
}
// fp16 exact split: a = hi + lo to ~2^-22
__device__ __forceinline__ void hsplit2(float a, float b, uint32_t& hi, uint32_t& lo) {
    __half ah = __float2half_rn(a);
    __half bh = __float2half_rn(b);
    float ar = a - __half2float(ah);
    float br = b - __half2float(bh);
    __half2 h; h.x = ah; h.y = bh;
    __half2 l; l.x = __float2half_rn(ar); l.y = __float2half_rn(br);
    hi = *reinterpret_cast<uint32_t*>(&h);
    lo = *reinterpret_cast<uint32_t*>(&l);
}
__device__ __forceinline__ uint32_t pack_h2(float a, float b) {
    __half2 h; h.x = __float2half_rn(a); h.y = __float2half_rn(b);
    return *reinterpret_cast<uint32_t*>(&h);
}
__device__ __forceinline__ uint32_t smem_u32(const void* p) {
    uint32_t a;
    asm("{ .reg .u64 t; cvta.to.shared.u64 t, %1; cvt.u32.u64 %0, t; }"
        : "=r"(a) : "l"(p));
    return a;
}
// L2-direct async copy (bypasses L1)
__device__ __forceinline__ void cp_async16_cg(uint32_t dst, const void* src, int srcsize) {
    asm volatile("cp.async.cg.shared.global [%0], [%1], 16, %2;"
                 :: "r"(dst), "l"(src), "r"(srcsize) : "memory");
}
#define CP_COMMIT() asm volatile("cp.async.commit_group;" ::: "memory")
#define CP_WAIT0()  asm volatile("cp.async.wait_group 0;" ::: "memory")

// mma.sync m16n8k16 fp16 -> f32 accumulate
__device__ __forceinline__ void mma16816h(float c[4], const uint32_t a[4],
                                          uint32_t b0, uint32_t b1) {
    asm volatile(
        "mma.sync.aligned.m16n8k16.row.col.f32.f16.f16.f32 "
        "{%0,%1,%2,%3}, {%4,%5,%6,%7}, {%8,%9}, {%0,%1,%2,%3};"
        : "+f"(c[0]), "+f"(c[1]), "+f"(c[2]), "+f"(c[3])
        : "r"(a[0]), "r"(a[1]), "r"(a[2]), "r"(a[3]), "r"(b0), "r"(b1));
}

// ---------------------------------------------------------------------------
// util1: clear idx_map (all threads) + prep w2 fp16 fragments (first 9216)
__global__ void util1_kernel(const float* __restrict__ w2) {
    int i = blockIdx.x * blockDim.x + threadIdx.x;
    if (i < HGRID * WGRID) g_idx_map[i] = -1;
    if (i < 9 * 4 * 8 * 32) {
        int lane = i & 31, nt = (i >> 5) & 7, kc = (i >> 8) & 3, tap = i >> 10;
        int n  = nt * 8 + (lane >> 2);
        int k0 = kc * 16 + (lane & 3) * 2;
        uint32_t p0 = pack_h2(w2[tap * 4096 + k0 * 64 + n],
                              w2[tap * 4096 + (k0 + 1) * 64 + n]);
        uint32_t p1 = pack_h2(w2[tap * 4096 + (k0 + 8) * 64 + n],
                              w2[tap * 4096 + (k0 + 9) * 64 + n]);
        g_w2h[i] = make_uint2(p0, p1);
    }
}

// util2: scatter coords + prep w3 fp16 frags (i<4096) + w1 fp16 frags ([4096,8192))
__global__ void util2_kernel(const int* __restrict__ coords,
                             const float* __restrict__ w3,
                             const float* __restrict__ w1, int n) {
    int i = blockIdx.x * blockDim.x + threadIdx.x;
    if (i < n) {
        int is64 = coords_is64(coords);
        g_idx_map[load_coord(coords, is64, i)] = i;
    }
    if (i < 4 * 4 * 8 * 32) {
        int lane = i & 31, nt = (i >> 5) & 7, kc = (i >> 8) & 3, cb = i >> 10;
        int nn = cb * 64 + nt * 8 + (lane >> 2);
        int k0 = kc * 16 + (lane & 3) * 2;
        uint32_t p0 = pack_h2(w3[k0 * 256 + nn], w3[(k0 + 1) * 256 + nn]);
        uint32_t p1 = pack_h2(w3[(k0 + 8) * 256 + nn], w3[(k0 + 9) * 256 + nn]);
        g_w3h[i] = make_uint2(p0, p1);
    } else if (i < 8192) {
        int j = i - 4096;
        int lane = j & 31, nt = (j >> 5) & 7, kc = j >> 8;   // kc 0..15
        int nn = nt * 8 + (lane >> 2);
        int k0 = kc * 16 + (lane & 3) * 2;
        uint32_t p0 = pack_h2(w1[k0 * 64 + nn], w1[(k0 + 1) * 64 + nn]);
        uint32_t p1 = pack_h2(w1[(k0 + 8) * 64 + nn], w1[(k0 + 9) * 64 + nn]);
        g_w1h[j] = make_uint2(p0, p1);
    }
}

// ---------------------------------------------------------------------------
// conv1 via fp16 2-term mma (feats exact-split + rounded w1);
// OUTPUT: plain fp16 rows (128B/site).
#define LDF 144
#define FPL (128 * LDF)
#define S1_SC 0
#define S1_F  512
#define S1_B  37376                     // 2 x 4096 -> ends 45568
#define S1_TOTAL 45568

__global__ void __launch_bounds__(256, 3) conv1_mma_kernel(
    const float* __restrict__ feats,
    const float* __restrict__ s1, const float* __restrict__ b1, int n)
{
    extern __shared__ __align__(128) char dsm1[];
    float* s_s1 = (float*)(dsm1 + S1_SC);
    float* s_b1 = s_s1 + 64;
    unsigned char* sF = (unsigned char*)(dsm1 + S1_F);
    uint2* Bsm = (uint2*)(dsm1 + S1_B);

    const int tid = threadIdx.x, wid = tid >> 5, lane = tid & 31;
    const int site0 = blockIdx.x * 128;
    const int rw = wid * 16;
    const int frow = tid >> 3, fc8 = tid & 7;

    if (tid < 64) { s_s1[tid] = s1[tid]; s_b1[tid] = b1[tid]; }

    const uint32_t f_sm = smem_u32(sF);
    const uint32_t b_sm = smem_u32(Bsm);

    auto issue_ck = [&](int ck) {
        uint32_t fdst = f_sm + (ck & 1) * FPL;
#pragma unroll
        for (int g = 0; g < 4; ++g) {
            int row = frow + g * 32;
            int site = site0 + row;
            const char* src = (const char*)feats +
                (size_t)(site < n ? site : 0) * 1024 + ck * 128 + fc8 * 16;
            cp_async16_cg(fdst + row * LDF + fc8 * 16, src, site < n ? 16 : 0);
        }
        const uint2* bs = g_w1h + (size_t)ck * 512 + tid * 2;   // 2 kc slices = 4KB
        uint32_t bd = b_sm + (ck & 1) * 4096 + tid * 16;
        cp_async16_cg(bd, bs, 16);
        CP_COMMIT();
    };

    float acc[8][4];
#pragma unroll
    for (int t = 0; t < 8; ++t)
#pragma unroll
        for (int j = 0; j < 4; ++j) acc[t][j] = 0.f;

    issue_ck(0);

#pragma unroll 1
    for (int ck = 0; ck < 8; ++ck) {
        CP_WAIT0();
        __syncthreads();
        if (ck < 7) issue_ck(ck + 1);

        const unsigned char* fb = sF + (ck & 1) * FPL;
        const uint2* Bcur = Bsm + (ck & 1) * 512;
#pragma unroll
        for (int kh = 0; kh < 2; ++kh) {
            uint32_t ab = (uint32_t)((rw + (lane >> 2)) * LDF + kh * 64 + (lane & 3) * 8);
            float2 p00 = *(const float2*)(fb + ab);
            float2 p10 = *(const float2*)(fb + ab + 8 * LDF);
            float2 p01 = *(const float2*)(fb + ab + 32);
            float2 p11 = *(const float2*)(fb + ab + 8 * LDF + 32);
            uint32_t ah[4], al[4];
            hsplit2(p00.x, p00.y, ah[0], al[0]);
            hsplit2(p10.x, p10.y, ah[1], al[1]);
            hsplit2(p01.x, p01.y, ah[2], al[2]);
            hsplit2(p11.x, p11.y, ah[3], al[3]);
#pragma unroll
            for (int nt = 0; nt < 8; ++nt) {
                uint2 b = Bcur[kh * 256 + nt * 32 + lane];
                mma16816h(acc[nt], ah, b.x, b.y);
                mma16816h(acc[nt], al, b.x, b.y);
            }
        }
    }
    __syncthreads();

    // epilogue: bn1 + relu, round to fp16, stage 128B rows, coalesced write
    uint32_t* sh = (uint32_t*)sF;   // 128 rows x 32 words (128B)
    {
        int r0 = rw + (lane >> 2);
        int n0 = (lane & 3) * 2;
#pragma unroll
        for (int nt = 0; nt < 8; ++nt) {
            int c0 = nt * 8 + n0;
            int wc = nt * 4 + (lane & 3);
            float v0 = fmaxf(fmaf(acc[nt][0], s_s1[c0],     s_b1[c0]),     0.f);
            float v1 = fmaxf(fmaf(acc[nt][1], s_s1[c0 + 1], s_b1[c0 + 1]), 0.f);
            float v2 = fmaxf(fmaf(acc[nt][2], s_s1[c0],     s_b1[c0]),     0.f);
            float v3 = fmaxf(fmaf(acc[nt][3], s_s1[c0 + 1], s_b1[c0 + 1]), 0.f);
            sh[r0 * 32 + wc]       = pack_h2(v0, v1);
            sh[(r0 + 8) * 32 + wc] = pack_h2(v2, v3);
        }
    }
    __syncthreads();
    {   // 8 lanes per 128B row, 32 rows per pass, 4 passes
        int chunk = tid & 7, rbase = tid >> 3;
#pragma unroll
        for (int it = 0; it < 4; ++it) {
            int row = rbase + it * 32;
            uint4 v = *(const uint4*)((const char*)sh + row * 128 + chunk * 16);
            *(uint4*)(g_h1b + (size_t)(site0 + row) * 128 + chunk * 16) = v;
        }
    }
}

// ---------------------------------------------------------------------------
// FUSED conv2 + conv3. conv2: pure fp16 (1 MMA/step); conv3: pure fp16
// (h2 rounded + rounded w3, 1 MMA/step). cp.async.cg double buffering.
#define APL 18432                       // A plane buffer: 128 rows * 144B
#define LDP 144
#define SM_SC    0                      // 2560
#define SM_NBR   2560                   // 4608 -> ends 7168
#define SM_A     7680                   // 2 * APL = 36864 -> ends 44544
#define SM_B     44544                  // 16384 (conv2 2x8KB / conv3 8KB) -> 60928
#define SM_TOTAL 60928

__global__ void __launch_bounds__(256) conv23_kernel(
    const int* __restrict__ coords,
    const float* __restrict__ s2, const float* __restrict__ b2,
    const float* __restrict__ feats,
    const float* __restrict__ s3, const float* __restrict__ b3,
    float* __restrict__ out, int n)
{
    extern __shared__ __align__(128) char dsm[];
    float* s_s2 = (float*)(dsm + SM_SC);
    float* s_b2 = s_s2 + 64;
    float* s_s3 = s_b2 + 64;
    float* s_b3 = s_s3 + 256;
    int*  s_nbr = (int*)(dsm + SM_NBR);
    unsigned char* Abuf = (unsigned char*)(dsm + SM_A);
    uint2* Bh2 = (uint2*)(dsm + SM_B);

    const int tid = threadIdx.x, wid = tid >> 5, lane = tid & 31;
    const int site0 = blockIdx.x * 128;
    const int rw = wid * 16;

    // gather mapping: 8 lanes per 128B h1 row; 4 rows per iter
    const int sub4  = lane >> 3;
    const int boff8 = (lane & 7) * 16;
    // epilogue mapping: 16 lanes per 256B f32 row
    const int sub  = lane >> 4;
    const int boff = (lane & 15) * 16;

    if (tid < 64) { s_s2[tid] = s2[tid]; s_b2[tid] = b2[tid]; }
    s_s3[tid] = s3[tid]; s_b3[tid] = b3[tid];
    if (tid < 128) {
#pragma unroll
        for (int t = 0; t < 9; ++t) s_nbr[t * 128 + tid] = -1;
        int site = site0 + tid;
        if (site < n) {
            int is64 = coords_is64(coords);
            int c = load_coord(coords, is64, site);
            int y = c / WGRID, x = c % WGRID;
#pragma unroll
            for (int t = 0; t < 9; ++t) {
                int ny = y + t / 3 - 1, nx = x + t % 3 - 1;
                if (ny >= 0 && ny < HGRID && nx >= 0 && nx < WGRID)
                    s_nbr[t * 128 + tid] = g_idx_map[ny * WGRID + nx];
            }
        }
    }
    __syncthreads();

    float acc[8][4];
#pragma unroll
    for (int t = 0; t < 8; ++t)
#pragma unroll
        for (int j = 0; j < 4; ++j) acc[t][j] = 0.f;

    const uint32_t a_sm = smem_u32(Abuf);
    const uint32_t b_sm = smem_u32(Bh2);

    auto issue_tap = [&](int t) {
        uint32_t abase = a_sm + (t & 1) * APL + boff8;
#pragma unroll
        for (int g = 0; g < 4; ++g) {
            int row = rw + g * 4 + sub4;
            int nb = s_nbr[t * 128 + row];
            const unsigned char* src = g_h1b + (size_t)(nb < 0 ? 0 : nb) * 128 + boff8;
            cp_async16_cg(abase + row * LDP, src, nb >= 0 ? 16 : 0);
        }
        const uint2* bs = g_w2h + (size_t)t * 1024 + tid * 4;
        uint32_t bd = b_sm + (t & 1) * 8192 + tid * 32;
        cp_async16_cg(bd, bs, 16);
        cp_async16_cg(bd + 16, bs + 2, 16);
        CP_COMMIT();
    };

    issue_tap(0);

    // ---------------- conv2: 9-tap, pure fp16, 1 MMA per step -------------
#pragma unroll 1
    for (int tap = 0; tap < 9; ++tap) {
        CP_WAIT0();
        __syncthreads();
        if (tap < 8) issue_tap(tap + 1);

        const unsigned char* wbase = Abuf + (tap & 1) * APL;
        const uint2* Bcur = Bh2 + (tap & 1) * 1024;
#pragma unroll
        for (int kc = 0; kc < 4; ++kc) {
            uint32_t ab = (uint32_t)((rw + (lane >> 2)) * LDP + kc * 32 + (lane & 3) * 4);
            uint32_t ah[4];
            ah[0] = *(const uint32_t*)(wbase + ab);
            ah[1] = *(const uint32_t*)(wbase + ab + 8 * LDP);
            ah[2] = *(const uint32_t*)(wbase + ab + 16);
            ah[3] = *(const uint32_t*)(wbase + ab + 8 * LDP + 16);
#pragma unroll
            for (int nt = 0; nt < 8; ++nt) {
                uint2 b = Bcur[kc * 256 + nt * 32 + lane];
                mma16816h(acc[nt], ah, b.x, b.y);
            }
        }
    }
    __syncthreads();   // all warps finish MMA(tap 8) before buffer reuse

    // --- bn2 + relu in registers; ROUND to fp16 -> conv3 A-frags ----------
    uint32_t fh[4][4];
    {
        const int n0 = (lane & 3) * 2;
#pragma unroll
        for (int kc = 0; kc < 4; ++kc) {
#pragma unroll
            for (int q = 0; q < 2; ++q) {
                int nt = 2 * kc + q;
                int c0 = nt * 8 + n0;
                float v0 = fmaxf(fmaf(acc[nt][0], s_s2[c0],     s_b2[c0]),     0.f);
                float v1 = fmaxf(fmaf(acc[nt][1], s_s2[c0 + 1], s_b2[c0 + 1]), 0.f);
                float v2 = fmaxf(fmaf(acc[nt][2], s_s2[c0],     s_b2[c0]),     0.f);
                float v3 = fmaxf(fmaf(acc[nt][3], s_s2[c0 + 1], s_b2[c0 + 1]), 0.f);
                fh[kc][2 * q]     = pack_h2(v0, v1);
                fh[kc][2 * q + 1] = pack_h2(v2, v3);
            }
        }
    }

    // ---------------- conv3: pure fp16, 4 column blocks -------------------
    float* stg = (float*)Abuf;   // 128 x 64 f32 staging = 32KB (fits 2*APL)
    {   // preload cb=0 B fragments
        const uint2* bs = g_w3h + tid * 4;
#pragma unroll
        for (int q = 0; q < 4; ++q) Bh2[tid * 4 + q] = bs[q];
    }
    __syncthreads();

#pragma unroll 1
    for (int cb = 0; cb < 4; ++cb) {
        float acc2[8][4];
#pragma unroll
        for (int t = 0; t < 8; ++t)
#pragma unroll
            for (int j = 0; j < 4; ++j) acc2[t][j] = 0.f;

#pragma unroll
        for (int kc = 0; kc < 4; ++kc) {
#pragma unroll
            for (int nt = 0; nt < 8; ++nt) {
                uint2 b = Bh2[kc * 256 + nt * 32 + lane];
                mma16816h(acc2[nt], fh[kc], b.x, b.y);
            }
        }
        __syncthreads();   // B reads done; stg free (prev write-out done)
        {
            int r0 = rw + (lane >> 2);
            int n0 = (lane & 3) * 2;
#pragma unroll
            for (int nt = 0; nt < 8; ++nt) {
                int c  = nt * 8 + n0;
                int cg = cb * 64 + c;
                stg[r0 * 64 + c]           = fmaf(acc2[nt][0], s_s3[cg],     s_b3[cg]);
                stg[r0 * 64 + c + 1]       = fmaf(acc2[nt][1], s_s3[cg + 1], s_b3[cg + 1]);
                stg[(r0 + 8) * 64 + c]     = fmaf(acc2[nt][2], s_s3[cg],     s_b3[cg]);
                stg[(r0 + 8) * 64 + c + 1] = fmaf(acc2[nt][3], s_s3[cg + 1], s_b3[cg + 1]);
            }
        }
        if (cb < 3) {   // stage next cb's B fragments
            const uint2* bs = g_w3h + (size_t)(cb + 1) * 1024 + tid * 4;
#pragma unroll
            for (int q = 0; q < 4; ++q) Bh2[tid * 4 + q] = bs[q];
        }
        __syncthreads();   // stg + next B visible
        {   // coalesced residual+relu+write: 16 lanes per 256B row
#pragma unroll
            for (int g = 0; g < 8; ++g) {
                int row = rw + g * 2 + sub;
                int site = site0 + row;
                if (site < n) {
                    float4 a = *(const float4*)((const char*)stg + row * 256 + boff);
                    float4 b = *(const float4*)((const char*)feats +
                                                (size_t)site * 1024 + cb * 256 + boff);
                    float4 o;
                    o.x = fmaxf(a.x + b.x, 0.f);
                    o.y = fmaxf(a.y + b.y, 0.f);
                    o.z = fmaxf(a.z + b.z, 0.f);
                    o.w = fmaxf(a.w + b.w, 0.f);
                    *(float4*)((char*)out + (size_t)site * 1024 + cb * 256 + boff) = o;
                }
            }
        }
    }
}

// ---------------------------------------------------------------------------
extern "C" void kernel_launch(void* const* d_in, const int* in_sizes, int n_in,
                              void* d_out, int out_size) {
    const float* feats  = (const float*)d_in[0];
    const int*   coords = (const int*)d_in[1];
    const float* w1     = (const float*)d_in[2];
    const float* w2     = (const float*)d_in[3];
    const float* w3     = (const float*)d_in[4];
    const float* s1     = (const float*)d_in[5];
    const float* b1     = (const float*)d_in[6];
    const float* s2     = (const float*)d_in[7];
    const float* b2     = (const float*)d_in[8];
    const float* s3     = (const float*)d_in[9];
    const float* b3     = (const float*)d_in[10];
    float* out = (float*)d_out;

    const int n = in_sizes[0] / 256;
    const int tiles = (n + 127) / 128;

    cudaFuncSetAttribute(conv1_mma_kernel,
                         cudaFuncAttributeMaxDynamicSharedMemorySize, S1_TOTAL);
    cudaFuncSetAttribute(conv23_kernel,
                         cudaFuncAttributeMaxDynamicSharedMemorySize, SM_TOTAL);

    // 4 launches; conv23 is launch #4 so ncu (-s/-c window) captures it.
    util1_kernel<<<(HGRID * WGRID + 255) / 256, 256>>>(w2);                   // #1
    util2_kernel<<<(max(n, 8192) + 255) / 256, 256>>>(coords, w3, w1, n);     // #2
    conv1_mma_kernel<<<tiles, 256, S1_TOTAL>>>(feats, s1, b1, n);             // #3
    conv23_kernel<<<tiles, 256, SM_TOTAL>>>(coords, s2, b2, feats, s3, b3, out, n);  // #4
}